// round 13
// baseline (speedup 1.0000x reference)
#include <cuda_runtime.h>
#include <cuda_bf16.h>
#include <math.h>
#include <stdint.h>

#define BATCH   2
#define SEQLEN  2048
#define DMODEL  1024
#define DINNER  2048
#define DSTATE  16
#define DCONV   4
#define M_ROWS  (BATCH * SEQLEN)   // 4096
#define NXZ     (2 * DINNER)       // 4096
#define CHUNK   32
#define NCHUNK  (M_ROWS / CHUNK)   // 128
#define NCH_B   (SEQLEN / CHUNK)   // 64
#define NPROJ   33
#define KSPLIT  4

// ---------------- scratch (static device arrays) ----------------
__device__ float g_xz[M_ROWS * NXZ];           // 64 MB
__device__ float g_xc[M_ROWS * DINNER];        // 32 MB
__device__ float g_y [M_ROWS * DINNER];        // y_local (scan) 32 MB
__device__ float g_projp[KSPLIT * M_ROWS * NPROJ];
__device__ float g_coef[M_ROWS * 48];
__device__ float g_delta[M_ROWS];
__device__ float g_wpre[M_ROWS * DSTATE];
__device__ float g_Ac[NCHUNK * DSTATE];
__device__ float g_hloc [NCHUNK * DINNER * DSTATE];
__device__ float g_hstart[NCHUNK * DINNER * DSTATE];
__device__ int   g_nonuni;

// split-bf16 operands
__device__ __nv_bfloat16 g_a1h[M_ROWS * DMODEL], g_a1l[M_ROWS * DMODEL];   // x hi/lo
__device__ __nv_bfloat16 g_w1h[NXZ * DMODEL],    g_w1l[NXZ * DMODEL];      // W_in^T [N][K]
__device__ __nv_bfloat16 g_yh [M_ROWS * DINNER], g_yl [M_ROWS * DINNER];   // y hi/lo
__device__ __nv_bfloat16 g_w2h[DMODEL * DINNER], g_w2l[DMODEL * DINNER];   // W_out^T [N][K]

// ---------------- helpers ----------------
__device__ __forceinline__ uint32_t smem_to_u32(const void* p) {
    uint32_t a;
    asm("{ .reg .u64 t; cvta.to.shared.u64 t, %1; cvt.u32.u64 %0, t; }" : "=r"(a) : "l"(p));
    return a;
}

__device__ __forceinline__ void ldsm_x4(uint32_t& r0, uint32_t& r1, uint32_t& r2, uint32_t& r3,
                                        uint32_t addr) {
    asm volatile("ldmatrix.sync.aligned.m8n8.x4.shared.b16 {%0,%1,%2,%3}, [%4];"
                 : "=r"(r0), "=r"(r1), "=r"(r2), "=r"(r3) : "r"(addr));
}

__device__ __forceinline__ void mma_bf16(float& d0, float& d1, float& d2, float& d3,
                                         uint32_t a0, uint32_t a1, uint32_t a2, uint32_t a3,
                                         uint32_t b0, uint32_t b1) {
    asm volatile("mma.sync.aligned.m16n8k16.row.col.f32.bf16.bf16.f32 "
                 "{%0,%1,%2,%3}, {%4,%5,%6,%7}, {%8,%9}, {%0,%1,%2,%3};"
                 : "+f"(d0), "+f"(d1), "+f"(d2), "+f"(d3)
                 : "r"(a0), "r"(a1), "r"(a2), "r"(a3), "r"(b0), "r"(b1));
}

__device__ __forceinline__ void cp_async16(uint32_t dst, const void* src) {
    asm volatile("cp.async.cg.shared.global [%0], [%1], 16;" :: "r"(dst), "l"(src));
}
#define CP_COMMIT() asm volatile("cp.async.commit_group;" ::: "memory")
#define CP_WAIT1()  asm volatile("cp.async.wait_group 1;" ::: "memory")

// ---------------------------------------------------------------------------
// Split-bf16 tensor-core GEMM via mma.sync (HMMA), cp.async double-buffered:
//   C[M,N] = (Ah+Al)[M,K] @ (Bh+Bl)[N,K]^T + bias
// 128x128 CTA tile, 16 warps (4m x 4n), warp tile 32x32 (2 m16 x 4 n8), KTILE=32.
// 3 passes: Ah*Bh + Ah*Bl + Al*Bh (fp32 accum). Rows padded to 40 bf16 (80B):
// ldmatrix 8-row phases hit banks {0,20,8,28,16,4,24,12} — conflict-free.
// ---------------------------------------------------------------------------
#define KTILE 32
#define ROWP  40                      // padded row length in bf16 (80 bytes)
#define MATB  (128 * ROWP * 2)        // 10240 bytes per matrix
#define STAGEB (4 * MATB)             // 40960 bytes per stage
#define MM_DSMEM (2 * STAGEB)         // 81920
#define MM_THREADS 512

__global__ __launch_bounds__(MM_THREADS)
void mm_tc_kernel(const __nv_bfloat16* __restrict__ Ah, const __nv_bfloat16* __restrict__ Al,
                  const __nv_bfloat16* __restrict__ Bh, const __nv_bfloat16* __restrict__ Bl,
                  const float* __restrict__ bias, float* __restrict__ C,
                  int M, int N, int K)
{
    extern __shared__ __align__(16) char dynsm[];
    const uint32_t sbase = smem_to_u32(dynsm);

    const int tid  = threadIdx.x;
    const int wid  = tid >> 5;          // 0..15
    const int lane = tid & 31;
    const int n0 = blockIdx.x * 128;
    const int m0 = blockIdx.y * 128;

    const int wm = wid >> 2;            // 0..3 -> m offset wm*32
    const int wn = wid & 3;             // 0..3 -> n offset wn*32

    float acc[2][4][4];                 // [mt][nt][frag]
#pragma unroll
    for (int i = 0; i < 2; i++)
#pragma unroll
        for (int j = 0; j < 4; j++)
#pragma unroll
            for (int q = 0; q < 4; q++) acc[i][j][q] = 0.f;

    // ldmatrix addressing (byte offsets inside one matrix)
    const uint32_t a_row  = (uint32_t)(wm * 32 + (lane & 15));
    const uint32_t a_coff = (uint32_t)((lane >> 4) * 16);
    const uint32_t b_row  = (uint32_t)(wn * 32 + (lane & 7) + ((lane >> 4) << 3));
    const uint32_t b_koff = (uint32_t)(((lane >> 3) & 1) * 16);

    const int nk = K / KTILE;

    // ---- prologue: async-load k-tile 0 into stage 0 ----
#pragma unroll
    for (int j = 0; j < 4; j++) {
        int i    = tid + j * MM_THREADS;   // 0..2047
        int mId  = i >> 9;
        int w    = i & 511;
        int row  = w >> 2;
        int c4   = w & 3;
        const __nv_bfloat16* src =
            (mId == 0) ? Ah : (mId == 1) ? Al : (mId == 2) ? Bh : Bl;
        const int r0 = (mId < 2) ? m0 : n0;
        cp_async16(sbase + mId * MATB + (uint32_t)(row * 80 + c4 * 16),
                   src + (size_t)(r0 + row) * K + c4 * 8);
    }
    CP_COMMIT();

    for (int kt = 0; kt < nk; kt++) {
        const int cur = kt & 1;
        if (kt + 1 < nk) {
            const int k1 = (kt + 1) * KTILE;
            const uint32_t stoff = (uint32_t)((cur ^ 1) * STAGEB);
#pragma unroll
            for (int j = 0; j < 4; j++) {
                int i    = tid + j * MM_THREADS;
                int mId  = i >> 9;
                int w    = i & 511;
                int row  = w >> 2;
                int c4   = w & 3;
                const __nv_bfloat16* src =
                    (mId == 0) ? Ah : (mId == 1) ? Al : (mId == 2) ? Bh : Bl;
                const int r0 = (mId < 2) ? m0 : n0;
                cp_async16(sbase + stoff + mId * MATB + (uint32_t)(row * 80 + c4 * 16),
                           src + (size_t)(r0 + row) * K + k1 + c4 * 8);
            }
        }
        CP_COMMIT();
        CP_WAIT1();
        __syncthreads();

        const uint32_t sb = sbase + (uint32_t)(cur * STAGEB);
#pragma unroll
        for (int kk = 0; kk < 2; kk++) {
            uint32_t ah[2][4], al[2][4];
#pragma unroll
            for (int mt = 0; mt < 2; mt++) {
                uint32_t off = (a_row + mt * 16) * 80 + kk * 32 + a_coff;
                ldsm_x4(ah[mt][0], ah[mt][1], ah[mt][2], ah[mt][3], sb + off);
                ldsm_x4(al[mt][0], al[mt][1], al[mt][2], al[mt][3], sb + MATB + off);
            }
            uint32_t bh[4][2], bl[4][2];
            {
                uint32_t off = b_row * 80 + kk * 32 + b_koff;
                uint32_t r0, r1, r2, r3;
                ldsm_x4(r0, r1, r2, r3, sb + 2 * MATB + off);
                bh[0][0] = r0; bh[0][1] = r1; bh[1][0] = r2; bh[1][1] = r3;
                ldsm_x4(r0, r1, r2, r3, sb + 3 * MATB + off);
                bl[0][0] = r0; bl[0][1] = r1; bl[1][0] = r2; bl[1][1] = r3;

                uint32_t off2 = (b_row + 16) * 80 + kk * 32 + b_koff;
                ldsm_x4(r0, r1, r2, r3, sb + 2 * MATB + off2);
                bh[2][0] = r0; bh[2][1] = r1; bh[3][0] = r2; bh[3][1] = r3;
                ldsm_x4(r0, r1, r2, r3, sb + 3 * MATB + off2);
                bl[2][0] = r0; bl[2][1] = r1; bl[3][0] = r2; bl[3][1] = r3;
            }
#pragma unroll
            for (int mt = 0; mt < 2; mt++)
#pragma unroll
                for (int nt = 0; nt < 4; nt++) {
                    float* d = acc[mt][nt];
                    mma_bf16(d[0], d[1], d[2], d[3],
                             ah[mt][0], ah[mt][1], ah[mt][2], ah[mt][3],
                             bh[nt][0], bh[nt][1]);
                    mma_bf16(d[0], d[1], d[2], d[3],
                             ah[mt][0], ah[mt][1], ah[mt][2], ah[mt][3],
                             bl[nt][0], bl[nt][1]);
                    mma_bf16(d[0], d[1], d[2], d[3],
                             al[mt][0], al[mt][1], al[mt][2], al[mt][3],
                             bh[nt][0], bh[nt][1]);
                }
        }
        __syncthreads();
    }

    // ---- epilogue: frag mapping c0 (r, c), c1 (r, c+1), c2 (r+8, c), c3 (r+8, c+1)
    const int rbase = m0 + wm * 32 + (lane >> 2);
    const int cbase = n0 + wn * 32 + (lane & 3) * 2;
#pragma unroll
    for (int mt = 0; mt < 2; mt++) {
#pragma unroll
        for (int nt = 0; nt < 4; nt++) {
            int r = rbase + mt * 16;
            int c = cbase + nt * 8;
            float b0 = bias[c], b1 = bias[c + 1];
            float2 o0 = { acc[mt][nt][0] + b0, acc[mt][nt][1] + b1 };
            float2 o1 = { acc[mt][nt][2] + b0, acc[mt][nt][3] + b1 };
            *(float2*)(C + (size_t)r * N + c)       = o0;
            *(float2*)(C + (size_t)(r + 8) * N + c) = o1;
        }
    }
}

// ---------------------------------------------------------------------------
// fp32 -> (hi, lo) bf16 split, elementwise, vectorized.
// ---------------------------------------------------------------------------
__global__ __launch_bounds__(256)
void split_kernel(const float* __restrict__ src, __nv_bfloat16* __restrict__ h,
                  __nv_bfloat16* __restrict__ l, int n4)
{
    int i = blockIdx.x * 256 + threadIdx.x;
    if (i >= n4) return;
    float4 v = ((const float4*)src)[i];
    float f[4] = { v.x, v.y, v.z, v.w };
    __nv_bfloat16 hh[4], ll[4];
#pragma unroll
    for (int j = 0; j < 4; j++) {
        hh[j] = __float2bfloat16(f[j]);
        ll[j] = __float2bfloat16(f[j] - __bfloat162float(hh[j]));
    }
    ((ushort4*)h)[i] = *(ushort4*)hh;
    ((ushort4*)l)[i] = *(ushort4*)ll;
}

// ---------------------------------------------------------------------------
// W[K][N] -> T[N][K] transpose with hi/lo bf16 split. 32x32 tiles.
// ---------------------------------------------------------------------------
__global__ __launch_bounds__(256)
void transpose_split_kernel(const float* __restrict__ W, __nv_bfloat16* __restrict__ Th,
                            __nv_bfloat16* __restrict__ Tl, int K, int N)
{
    __shared__ float tile[32][33];
    const int nb = blockIdx.x * 32;
    const int kb = blockIdx.y * 32;
    const int tx = threadIdx.x & 31;
    const int ty = threadIdx.x >> 5;
#pragma unroll
    for (int i = 0; i < 32; i += 8)
        tile[ty + i][tx] = W[(size_t)(kb + ty + i) * N + nb + tx];
    __syncthreads();
#pragma unroll
    for (int i = 0; i < 32; i += 8) {
        float v = tile[tx][ty + i];
        __nv_bfloat16 h = __float2bfloat16(v);
        __nv_bfloat16 l = __float2bfloat16(v - __bfloat162float(h));
        Th[(size_t)(nb + ty + i) * K + kb + tx] = h;
        Tl[(size_t)(nb + ty + i) * K + kb + tx] = l;
    }
}

// ---------------------------------------------------------------------------
// Causal depthwise conv (width 4) + SiLU.
// ---------------------------------------------------------------------------
__global__ __launch_bounds__(256)
void conv_silu_kernel(const float* __restrict__ conv_w, const float* __restrict__ conv_b)
{
    const int m = blockIdx.y;
    const int d = blockIdx.x * 256 + threadIdx.x;
    const int t = m & (SEQLEN - 1);

    float4 w = *(const float4*)(conv_w + d * 4);
    float acc = conv_b[d];
    const float* base = g_xz + (size_t)m * NXZ + d;

    if (t >= 3) {
        acc = fmaf(base[-3 * NXZ], w.x, acc);
        acc = fmaf(base[-2 * NXZ], w.y, acc);
        acc = fmaf(base[-1 * NXZ], w.z, acc);
        acc = fmaf(base[0],        w.w, acc);
    } else {
        const float wk[4] = { w.x, w.y, w.z, w.w };
#pragma unroll
        for (int k = 0; k < 4; k++) {
            int ts = t - 3 + k;
            if (ts >= 0) acc = fmaf(base[(k - 3) * NXZ], wk[k], acc);
        }
    }
    float s = acc / (1.f + expf(-acc));
    g_xc[(size_t)m * DINNER + d] = s;
}

// ---------------------------------------------------------------------------
__global__ void check_kernel(const float* __restrict__ A_log)
{
    int idx = blockIdx.x * blockDim.x + threadIdx.x;
    if (idx < DINNER * DSTATE) {
        if (A_log[idx] != A_log[idx & 15]) atomicOr(&g_nonuni, 1);
    }
}

// ---------------------------------------------------------------------------
// proj partials: slice ks covers K range [ks*512, ks*512+512).
// ---------------------------------------------------------------------------
#define PBK 64
__global__ __launch_bounds__(256)
void proj_gemm_kernel(const float* __restrict__ W_xproj)
{
    __shared__ float As[PBK][33];
    __shared__ float Ws[PBK][36];

    const int tid = threadIdx.x;
    const int m0  = blockIdx.x * 32;
    const int ks  = blockIdx.y;
    const int kb  = ks * (DINNER / KSPLIT);

    const int r  = tid & 31;
    const int tc = tid >> 5;

    float acc[4] = {0.f, 0.f, 0.f, 0.f};
    float acc32  = 0.f;

    for (int k0 = kb; k0 < kb + DINNER / KSPLIT; k0 += PBK) {
#pragma unroll
        for (int i = 0; i < 2; i++) {
            int f    = tid + i * 256;
            int row  = f >> 4;
            int col4 = f & 15;
            float4 v = *(const float4*)(g_xc + (size_t)(m0 + row) * DINNER + k0 + col4 * 4);
            As[col4 * 4 + 0][row] = v.x;
            As[col4 * 4 + 1][row] = v.y;
            As[col4 * 4 + 2][row] = v.z;
            As[col4 * 4 + 3][row] = v.w;
        }
        for (int idx = tid; idx < PBK * NPROJ; idx += 256) {
            int k = idx / NPROJ;
            int j = idx - k * NPROJ;
            Ws[k][j] = W_xproj[(size_t)(k0 + k) * NPROJ + j];
        }
        __syncthreads();

#pragma unroll 8
        for (int k = 0; k < PBK; k++) {
            float a  = As[k][r];
            float4 w = *(const float4*)(&Ws[k][tc * 4]);
            acc[0] = fmaf(a, w.x, acc[0]);
            acc[1] = fmaf(a, w.y, acc[1]);
            acc[2] = fmaf(a, w.z, acc[2]);
            acc[3] = fmaf(a, w.w, acc[3]);
            if (tc == 0) acc32 = fmaf(a, Ws[k][32], acc32);
        }
        __syncthreads();
    }

    float* prow = g_projp + ((size_t)ks * M_ROWS + m0 + r) * NPROJ;
#pragma unroll
    for (int jj = 0; jj < 4; jj++)
        prow[tc * 4 + jj] = acc[jj];
    if (tc == 0) prow[32] = acc32;
}

// ---------------------------------------------------------------------------
// Coefficients (sums the KSPLIT partials). One thread per (m, n).
// ---------------------------------------------------------------------------
__global__ __launch_bounds__(256)
void coef_kernel(const float* __restrict__ A_log)
{
    const int idx = blockIdx.x * 256 + threadIdx.x;
    const int m = idx >> 4;
    const int n = idx & 15;

    float pn = 0.f, pc = 0.f, pd = 0.f;
#pragma unroll
    for (int s = 0; s < KSPLIT; s++) {
        const float* p = g_projp + ((size_t)s * M_ROWS + m) * NPROJ;
        pn += p[n];
        pc += p[16 + n];
        pd += p[32];
    }
    float delta = (pd > 20.f) ? pd : log1pf(expf(pd));

    float An = -expf(A_log[n]);
    g_coef[(size_t)m * 48 + n]      = expf(delta * An);
    g_coef[(size_t)m * 48 + 16 + n] = delta * pn;
    g_coef[(size_t)m * 48 + 32 + n] = pc;
    if (n == 0) g_delta[m] = delta;
}

// ---------------------------------------------------------------------------
__global__ void chunkprod_kernel()
{
    const int c = blockIdx.x;
    const int n = threadIdx.x;
    const int mbase = c * CHUNK;
    float P = 1.f;
#pragma unroll
    for (int tt = 0; tt < CHUNK; tt++) {
        const int m = mbase + tt;
        P *= g_coef[(size_t)m * 48 + n];
        g_wpre[(size_t)m * DSTATE + n] = g_coef[(size_t)m * 48 + 32 + n] * P;
    }
    g_Ac[c * DSTATE + n] = P;
}

// ---------------------------------------------------------------------------
__global__ __launch_bounds__(32)
void scan_local_kernel()
{
    const int lane  = threadIdx.x;
    const int c     = blockIdx.x >> 6;
    const int d     = (blockIdx.x & 63) * 32 + lane;
    const int mbase = c * CHUNK;

    __shared__ float4 sc[CHUNK][12];
    __shared__ float  sx[CHUNK][32];

    {
        const float4* src = (const float4*)(g_coef + (size_t)mbase * 48);
        float4* dst = (float4*)sc;
#pragma unroll
        for (int i = 0; i < 12; i++)
            dst[lane + i * 32] = src[lane + i * 32];
#pragma unroll
        for (int i = 0; i < CHUNK; i++)
            sx[i][lane] = g_xc[(size_t)(mbase + i) * DINNER + d];
    }
    __syncwarp();

    float h[16];
#pragma unroll
    for (int n = 0; n < 16; n++) h[n] = 0.f;

#pragma unroll 8
    for (int tt = 0; tt < CHUNK; tt++) {
        const float x = sx[tt][lane];
        float y = 0.f;
#pragma unroll
        for (int q = 0; q < 4; q++) {
            float4 a4 = sc[tt][q];
            float4 b4 = sc[tt][4 + q];
            float4 c4 = sc[tt][8 + q];
            h[4*q+0] = fmaf(a4.x, h[4*q+0], b4.x * x); y = fmaf(h[4*q+0], c4.x, y);
            h[4*q+1] = fmaf(a4.y, h[4*q+1], b4.y * x); y = fmaf(h[4*q+1], c4.y, y);
            h[4*q+2] = fmaf(a4.z, h[4*q+2], b4.z * x); y = fmaf(h[4*q+2], c4.z, y);
            h[4*q+3] = fmaf(a4.w, h[4*q+3], b4.w * x); y = fmaf(h[4*q+3], c4.w, y);
        }
        g_y[(size_t)(mbase + tt) * DINNER + d] = y;
    }

    float* hl = g_hloc + ((size_t)c * DINNER + d) * DSTATE;
#pragma unroll
    for (int q = 0; q < 4; q++)
        *(float4*)(hl + 4 * q) = make_float4(h[4*q], h[4*q+1], h[4*q+2], h[4*q+3]);
}

// ---------------------------------------------------------------------------
__global__ __launch_bounds__(256)
void carry_kernel()
{
    const int idx = blockIdx.x * 256 + threadIdx.x;
    const int b = idx >> 15;
    const int d = (idx >> 4) & (DINNER - 1);
    const int n = idx & 15;

    float h = 0.f;
    for (int cl = 0; cl < NCH_B; cl++) {
        const int c = b * NCH_B + cl;
        const size_t off = ((size_t)c * DINNER + d) * DSTATE + n;
        g_hstart[off] = h;
        h = fmaf(g_Ac[c * DSTATE + n], h, g_hloc[off]);
    }
}

// ---------------------------------------------------------------------------
// Combine + gated epilogue, FUSED with y hi/lo bf16 split (writes yh/yl).
// ---------------------------------------------------------------------------
__global__ __launch_bounds__(32)
void finish_kernel(const float* __restrict__ D_param)
{
    const int lane  = threadIdx.x;
    const int c     = blockIdx.x >> 6;
    const int d     = (blockIdx.x & 63) * 32 + lane;
    const int mbase = c * CHUNK;

    __shared__ float4 sw[CHUNK * 4];
    {
        const float4* src = (const float4*)(g_wpre + (size_t)mbase * DSTATE);
#pragma unroll
        for (int i = 0; i < 4; i++)
            sw[lane + i * 32] = src[lane + i * 32];
    }

    float hs[16];
    {
        const float* hp = g_hstart + ((size_t)c * DINNER + d) * DSTATE;
#pragma unroll
        for (int q = 0; q < 4; q++) {
            float4 v = *(const float4*)(hp + 4 * q);
            hs[4*q] = v.x; hs[4*q+1] = v.y; hs[4*q+2] = v.z; hs[4*q+3] = v.w;
        }
    }
    const float Dp = D_param[d];
    __syncwarp();

#pragma unroll 8
    for (int tt = 0; tt < CHUNK; tt++) {
        const int m = mbase + tt;
        float y = g_y[(size_t)m * DINNER + d];
#pragma unroll
        for (int q = 0; q < 4; q++) {
            float4 w4 = sw[tt * 4 + q];
            y = fmaf(w4.x, hs[4*q+0], y);
            y = fmaf(w4.y, hs[4*q+1], y);
            y = fmaf(w4.z, hs[4*q+2], y);
            y = fmaf(w4.w, hs[4*q+3], y);
        }
        const float x = g_xc[(size_t)m * DINNER + d];
        const float z = g_xz[(size_t)m * NXZ + DINNER + d];
        const float sz = z / (1.f + expf(-z));
        const float yv = (y + x * Dp) * sz;
        __nv_bfloat16 hh = __float2bfloat16(yv);
        __nv_bfloat16 ll = __float2bfloat16(yv - __bfloat162float(hh));
        g_yh[(size_t)m * DINNER + d] = hh;
        g_yl[(size_t)m * DINNER + d] = ll;
    }
}

// ---------------------------------------------------------------------------
// Fallback: full sequential scan (only if A non-uniform). Writes yh/yl.
// ---------------------------------------------------------------------------
__global__ __launch_bounds__(32)
void scan_fallback_kernel(const float* __restrict__ D_param, const float* __restrict__ A_log)
{
    if (*((volatile int*)&g_nonuni) == 0) return;

    const int lane  = threadIdx.x;
    const int b     = blockIdx.x >> 6;
    const int d     = (blockIdx.x & 63) * 32 + lane;
    const int mbase = b * SEQLEN;

    const float Dp = D_param[d];
    float Aloc[16];
#pragma unroll
    for (int n = 0; n < 16; n++) Aloc[n] = -expf(A_log[d * 16 + n]);

    float h[16];
#pragma unroll
    for (int n = 0; n < 16; n++) h[n] = 0.f;

    __shared__ float4 sc[32][12];

    for (int t0 = 0; t0 < SEQLEN; t0 += 32) {
        __syncthreads();
        const float4* src = (const float4*)(g_coef + (size_t)(mbase + t0) * 48);
        float4* dst = (float4*)sc;
#pragma unroll
        for (int i = 0; i < 12; i++)
            dst[lane + i * 32] = src[lane + i * 32];
        __syncthreads();

        for (int tt = 0; tt < 32; tt++) {
            const int m = mbase + t0 + tt;
            const float x = g_xc[(size_t)m * DINNER + d];
            const float dlt = g_delta[m];
            float y = 0.f;
#pragma unroll
            for (int q = 0; q < 4; q++) {
                float4 b4 = sc[tt][4 + q];
                float4 c4 = sc[tt][8 + q];
                float a0 = expf(dlt * Aloc[4*q+0]);
                float a1 = expf(dlt * Aloc[4*q+1]);
                float a2 = expf(dlt * Aloc[4*q+2]);
                float a3 = expf(dlt * Aloc[4*q+3]);
                h[4*q+0] = fmaf(a0, h[4*q+0], b4.x * x); y = fmaf(h[4*q+0], c4.x, y);
                h[4*q+1] = fmaf(a1, h[4*q+1], b4.y * x); y = fmaf(h[4*q+1], c4.y, y);
                h[4*q+2] = fmaf(a2, h[4*q+2], b4.z * x); y = fmaf(h[4*q+2], c4.z, y);
                h[4*q+3] = fmaf(a3, h[4*q+3], b4.w * x); y = fmaf(h[4*q+3], c4.w, y);
            }
            float z  = g_xz[(size_t)m * NXZ + DINNER + d];
            float sz = z / (1.f + expf(-z));
            const float yv = (y + x * Dp) * sz;
            __nv_bfloat16 hh = __float2bfloat16(yv);
            __nv_bfloat16 ll = __float2bfloat16(yv - __bfloat162float(hh));
            g_yh[(size_t)m * DINNER + d] = hh;
            g_yl[(size_t)m * DINNER + d] = ll;
        }
    }
}

// ---------------------------------------------------------------------------
extern "C" void kernel_launch(void* const* d_in, const int* in_sizes, int n_in,
                              void* d_out, int out_size)
{
    const float* x       = (const float*)d_in[0];
    const float* W_in    = (const float*)d_in[1];
    const float* b_in    = (const float*)d_in[2];
    const float* conv_w  = (const float*)d_in[3];
    const float* conv_b  = (const float*)d_in[4];
    const float* W_xproj = (const float*)d_in[5];
    const float* A_log   = (const float*)d_in[6];
    const float* D_param = (const float*)d_in[7];
    const float* W_out   = (const float*)d_in[8];
    const float* b_out   = (const float*)d_in[9];
    float* out = (float*)d_out;

    float *p_xz;
    void  *p_flag;
    __nv_bfloat16 *p_a1h, *p_a1l, *p_w1h, *p_w1l, *p_yh, *p_yl, *p_w2h, *p_w2l;
    cudaGetSymbolAddress((void**)&p_xz,  g_xz);
    cudaGetSymbolAddress(&p_flag, g_nonuni);
    cudaGetSymbolAddress((void**)&p_a1h, g_a1h);
    cudaGetSymbolAddress((void**)&p_a1l, g_a1l);
    cudaGetSymbolAddress((void**)&p_w1h, g_w1h);
    cudaGetSymbolAddress((void**)&p_w1l, g_w1l);
    cudaGetSymbolAddress((void**)&p_yh,  g_yh);
    cudaGetSymbolAddress((void**)&p_yl,  g_yl);
    cudaGetSymbolAddress((void**)&p_w2h, g_w2h);
    cudaGetSymbolAddress((void**)&p_w2l, g_w2l);

    cudaFuncSetAttribute(mm_tc_kernel, cudaFuncAttributeMaxDynamicSharedMemorySize,
                         MM_DSMEM);

    // 0) operand conversions
    split_kernel<<<(M_ROWS * DMODEL / 4 + 255) / 256, 256>>>(x, p_a1h, p_a1l,
                                                             M_ROWS * DMODEL / 4);
    transpose_split_kernel<<<dim3(NXZ / 32, DMODEL / 32), 256>>>(W_in, p_w1h, p_w1l,
                                                                 DMODEL, NXZ);
    transpose_split_kernel<<<dim3(DMODEL / 32, DINNER / 32), 256>>>(W_out, p_w2h, p_w2l,
                                                                    DINNER, DMODEL);
    // 1) xz = x @ W_in + b_in  (HMMA split-bf16, cp.async pipelined)
    mm_tc_kernel<<<dim3(NXZ / 128, M_ROWS / 128), MM_THREADS, MM_DSMEM>>>(
        p_a1h, p_a1l, p_w1h, p_w1l, b_in, p_xz, M_ROWS, NXZ, DMODEL);
    // 2) conv + silu -> g_xc
    conv_silu_kernel<<<dim3(DINNER / 256, M_ROWS), 256>>>(conv_w, conv_b);
    // 3) uniformity check
    cudaMemsetAsync(p_flag, 0, sizeof(int));
    check_kernel<<<(DINNER * DSTATE + 255) / 256, 256>>>(A_log);
    // 4) projection (split-K) + coefficients
    proj_gemm_kernel<<<dim3(M_ROWS / 32, KSPLIT), 256>>>(W_xproj);
    coef_kernel<<<(M_ROWS * DSTATE) / 256, 256>>>(A_log);
    // 5) chunk prefix products
    chunkprod_kernel<<<NCHUNK, DSTATE>>>();
    // 6) local scans
    scan_local_kernel<<<NCHUNK * (DINNER / 32), 32>>>();
    // 7) carry scan
    carry_kernel<<<(BATCH * DINNER * DSTATE) / 256, 256>>>();
    // 8) combine + gated epilogue + fused y split -> yh/yl
    finish_kernel<<<NCHUNK * (DINNER / 32), 32>>>(D_param);
    // 9) fallback (early-exits when A uniform)
    scan_fallback_kernel<<<128, 32>>>(D_param, A_log);
    // 10) out = y @ W_out + b_out (HMMA pipelined)
    mm_tc_kernel<<<dim3(DMODEL / 128, M_ROWS / 128), MM_THREADS, MM_DSMEM>>>(
        p_yh, p_yl, p_w2h, p_w2l, b_out, out, M_ROWS, DMODEL, DINNER);
}

// round 14
// speedup vs baseline: 1.1860x; 1.1860x over previous
#include <cuda_runtime.h>
#include <cuda_bf16.h>
#include <math.h>
#include <stdint.h>

#define BATCH   2
#define SEQLEN  2048
#define DMODEL  1024
#define DINNER  2048
#define DSTATE  16
#define DCONV   4
#define M_ROWS  (BATCH * SEQLEN)   // 4096
#define NXZ     (2 * DINNER)       // 4096
#define CHUNK   32
#define NCHUNK  (M_ROWS / CHUNK)   // 128
#define NCH_B   (SEQLEN / CHUNK)   // 64
#define NPROJ   33
#define KSPLIT  4

// ---------------- scratch (static device arrays) ----------------
__device__ float g_xz[M_ROWS * NXZ];           // 64 MB
__device__ float g_xc[M_ROWS * DINNER];        // 32 MB
__device__ float g_y [M_ROWS * DINNER];        // y_local (scan) 32 MB
__device__ float g_projp[KSPLIT * M_ROWS * NPROJ];
__device__ float g_coef[M_ROWS * 48];
__device__ float g_delta[M_ROWS];
__device__ float g_wpre[M_ROWS * DSTATE];
__device__ float g_Ac[NCHUNK * DSTATE];
__device__ float g_hloc [NCHUNK * DINNER * DSTATE];
__device__ float g_hstart[NCHUNK * DINNER * DSTATE];
__device__ int   g_nonuni;

// split-bf16 operands
__device__ __nv_bfloat16 g_a1h[M_ROWS * DMODEL], g_a1l[M_ROWS * DMODEL];   // x hi/lo
__device__ __nv_bfloat16 g_w1h[NXZ * DMODEL],    g_w1l[NXZ * DMODEL];      // W_in^T [N][K]
__device__ __nv_bfloat16 g_yh [M_ROWS * DINNER], g_yl [M_ROWS * DINNER];   // y hi/lo
__device__ __nv_bfloat16 g_w2h[DMODEL * DINNER], g_w2l[DMODEL * DINNER];   // W_out^T [N][K]

// ---------------- helpers ----------------
__device__ __forceinline__ uint32_t smem_to_u32(const void* p) {
    uint32_t a;
    asm("{ .reg .u64 t; cvta.to.shared.u64 t, %1; cvt.u32.u64 %0, t; }" : "=r"(a) : "l"(p));
    return a;
}

__device__ __forceinline__ void ldsm_x4(uint32_t& r0, uint32_t& r1, uint32_t& r2, uint32_t& r3,
                                        uint32_t addr) {
    asm volatile("ldmatrix.sync.aligned.m8n8.x4.shared.b16 {%0,%1,%2,%3}, [%4];"
                 : "=r"(r0), "=r"(r1), "=r"(r2), "=r"(r3) : "r"(addr));
}

__device__ __forceinline__ void mma_bf16(float& d0, float& d1, float& d2, float& d3,
                                         uint32_t a0, uint32_t a1, uint32_t a2, uint32_t a3,
                                         uint32_t b0, uint32_t b1) {
    asm volatile("mma.sync.aligned.m16n8k16.row.col.f32.bf16.bf16.f32 "
                 "{%0,%1,%2,%3}, {%4,%5,%6,%7}, {%8,%9}, {%0,%1,%2,%3};"
                 : "+f"(d0), "+f"(d1), "+f"(d2), "+f"(d3)
                 : "r"(a0), "r"(a1), "r"(a2), "r"(a3), "r"(b0), "r"(b1));
}

__device__ __forceinline__ void cp_async16(uint32_t dst, const void* src) {
    asm volatile("cp.async.cg.shared.global [%0], [%1], 16;" :: "r"(dst), "l"(src));
}
#define CP_COMMIT() asm volatile("cp.async.commit_group;" ::: "memory")
#define CP_WAIT1()  asm volatile("cp.async.wait_group 1;" ::: "memory")

// ---------------------------------------------------------------------------
// Split-bf16 tensor-core GEMM via mma.sync (HMMA), cp.async double-buffered.
// PROVEN SHAPE (R11): 128x128 CTA tile, 256 threads, 8 warps (4m x 2n),
// warp tile 32x64 (2 m16 x 8 n8), KTILE=32, two 40KB stages -> 2 CTAs/SM.
// 3 passes: Ah*Bh + Ah*Bl + Al*Bh (fp32 accum). Rows padded to 40 bf16 (80B):
// ldmatrix 8-row phases hit banks {0,20,8,28,16,4,24,12} — conflict-free.
// ---------------------------------------------------------------------------
#define KTILE 32
#define ROWP  40                      // padded row length in bf16 (80 bytes)
#define MATB  (128 * ROWP * 2)        // 10240 bytes per matrix
#define STAGEB (4 * MATB)             // 40960 bytes per stage
#define MM_DSMEM (2 * STAGEB)         // 81920

__global__ __launch_bounds__(256)
void mm_tc_kernel(const __nv_bfloat16* __restrict__ Ah, const __nv_bfloat16* __restrict__ Al,
                  const __nv_bfloat16* __restrict__ Bh, const __nv_bfloat16* __restrict__ Bl,
                  const float* __restrict__ bias, float* __restrict__ C,
                  int M, int N, int K)
{
    extern __shared__ __align__(16) char dynsm[];
    const uint32_t sbase = smem_to_u32(dynsm);

    const int tid  = threadIdx.x;
    const int wid  = tid >> 5;
    const int lane = tid & 31;
    const int n0 = blockIdx.x * 128;
    const int m0 = blockIdx.y * 128;

    const int wm = wid >> 1;        // 0..3 -> m offset wm*32
    const int wn = wid & 1;         // 0..1 -> n offset wn*64

    float acc[2][8][4];             // [mt][nt][frag]
#pragma unroll
    for (int i = 0; i < 2; i++)
#pragma unroll
        for (int j = 0; j < 8; j++)
#pragma unroll
            for (int q = 0; q < 4; q++) acc[i][j][q] = 0.f;

    const uint32_t a_row  = (uint32_t)(wm * 32 + (lane & 15));
    const uint32_t a_coff = (uint32_t)((lane >> 4) * 16);
    const uint32_t b_row  = (uint32_t)(wn * 64 + (lane & 7) + ((lane >> 4) << 3));
    const uint32_t b_koff = (uint32_t)(((lane >> 3) & 1) * 16);

    const int nk = K / KTILE;

    // ---- prologue: async-load k-tile 0 into stage 0 ----
#pragma unroll
    for (int j = 0; j < 8; j++) {
        int i    = tid + j * 256;
        int mId  = i >> 9;
        int w    = i & 511;
        int row  = w >> 2;
        int c4   = w & 3;
        const __nv_bfloat16* src =
            (mId == 0) ? Ah : (mId == 1) ? Al : (mId == 2) ? Bh : Bl;
        const int r0 = (mId < 2) ? m0 : n0;
        cp_async16(sbase + mId * MATB + (uint32_t)(row * 80 + c4 * 16),
                   src + (size_t)(r0 + row) * K + c4 * 8);
    }
    CP_COMMIT();

    for (int kt = 0; kt < nk; kt++) {
        const int cur = kt & 1;
        if (kt + 1 < nk) {
            const int k1 = (kt + 1) * KTILE;
            const uint32_t stoff = (uint32_t)((cur ^ 1) * STAGEB);
#pragma unroll
            for (int j = 0; j < 8; j++) {
                int i    = tid + j * 256;
                int mId  = i >> 9;
                int w    = i & 511;
                int row  = w >> 2;
                int c4   = w & 3;
                const __nv_bfloat16* src =
                    (mId == 0) ? Ah : (mId == 1) ? Al : (mId == 2) ? Bh : Bl;
                const int r0 = (mId < 2) ? m0 : n0;
                cp_async16(sbase + stoff + mId * MATB + (uint32_t)(row * 80 + c4 * 16),
                           src + (size_t)(r0 + row) * K + k1 + c4 * 8);
            }
        }
        CP_COMMIT();
        CP_WAIT1();
        __syncthreads();

        const uint32_t sb = sbase + (uint32_t)(cur * STAGEB);
#pragma unroll
        for (int kk = 0; kk < 2; kk++) {
            uint32_t ah[2][4], al[2][4];
#pragma unroll
            for (int mt = 0; mt < 2; mt++) {
                uint32_t off = (a_row + mt * 16) * 80 + kk * 32 + a_coff;
                ldsm_x4(ah[mt][0], ah[mt][1], ah[mt][2], ah[mt][3], sb + off);
                ldsm_x4(al[mt][0], al[mt][1], al[mt][2], al[mt][3], sb + MATB + off);
            }
            uint32_t bh[8][2], bl[8][2];
#pragma unroll
            for (int np = 0; np < 4; np++) {
                uint32_t off = (b_row + np * 16) * 80 + kk * 32 + b_koff;
                uint32_t r0, r1, r2, r3;
                ldsm_x4(r0, r1, r2, r3, sb + 2 * MATB + off);
                bh[np*2][0] = r0; bh[np*2][1] = r1; bh[np*2+1][0] = r2; bh[np*2+1][1] = r3;
                ldsm_x4(r0, r1, r2, r3, sb + 3 * MATB + off);
                bl[np*2][0] = r0; bl[np*2][1] = r1; bl[np*2+1][0] = r2; bl[np*2+1][1] = r3;
            }
#pragma unroll
            for (int mt = 0; mt < 2; mt++)
#pragma unroll
                for (int nt = 0; nt < 8; nt++) {
                    float* d = acc[mt][nt];
                    mma_bf16(d[0], d[1], d[2], d[3],
                             ah[mt][0], ah[mt][1], ah[mt][2], ah[mt][3],
                             bh[nt][0], bh[nt][1]);
                    mma_bf16(d[0], d[1], d[2], d[3],
                             ah[mt][0], ah[mt][1], ah[mt][2], ah[mt][3],
                             bl[nt][0], bl[nt][1]);
                    mma_bf16(d[0], d[1], d[2], d[3],
                             al[mt][0], al[mt][1], al[mt][2], al[mt][3],
                             bh[nt][0], bh[nt][1]);
                }
        }
        __syncthreads();
    }

    // ---- epilogue: frag mapping c0 (r, c), c1 (r, c+1), c2 (r+8, c), c3 (r+8, c+1)
    const int rbase = m0 + wm * 32 + (lane >> 2);
    const int cbase = n0 + wn * 64 + (lane & 3) * 2;
#pragma unroll
    for (int mt = 0; mt < 2; mt++) {
#pragma unroll
        for (int nt = 0; nt < 8; nt++) {
            int r = rbase + mt * 16;
            int c = cbase + nt * 8;
            float b0 = bias[c], b1 = bias[c + 1];
            float2 o0 = { acc[mt][nt][0] + b0, acc[mt][nt][1] + b1 };
            float2 o1 = { acc[mt][nt][2] + b0, acc[mt][nt][3] + b1 };
            *(float2*)(C + (size_t)r * N + c)       = o0;
            *(float2*)(C + (size_t)(r + 8) * N + c) = o1;
        }
    }
}

// ---------------------------------------------------------------------------
// fp32 -> (hi, lo) bf16 split, elementwise, vectorized.
// ---------------------------------------------------------------------------
__global__ __launch_bounds__(256)
void split_kernel(const float* __restrict__ src, __nv_bfloat16* __restrict__ h,
                  __nv_bfloat16* __restrict__ l, int n4)
{
    int i = blockIdx.x * 256 + threadIdx.x;
    if (i >= n4) return;
    float4 v = ((const float4*)src)[i];
    float f[4] = { v.x, v.y, v.z, v.w };
    __nv_bfloat16 hh[4], ll[4];
#pragma unroll
    for (int j = 0; j < 4; j++) {
        hh[j] = __float2bfloat16(f[j]);
        ll[j] = __float2bfloat16(f[j] - __bfloat162float(hh[j]));
    }
    ((ushort4*)h)[i] = *(ushort4*)hh;
    ((ushort4*)l)[i] = *(ushort4*)ll;
}

// ---------------------------------------------------------------------------
// W[K][N] -> T[N][K] transpose with hi/lo bf16 split. 32x32 tiles.
// ---------------------------------------------------------------------------
__global__ __launch_bounds__(256)
void transpose_split_kernel(const float* __restrict__ W, __nv_bfloat16* __restrict__ Th,
                            __nv_bfloat16* __restrict__ Tl, int K, int N)
{
    __shared__ float tile[32][33];
    const int nb = blockIdx.x * 32;
    const int kb = blockIdx.y * 32;
    const int tx = threadIdx.x & 31;
    const int ty = threadIdx.x >> 5;
#pragma unroll
    for (int i = 0; i < 32; i += 8)
        tile[ty + i][tx] = W[(size_t)(kb + ty + i) * N + nb + tx];
    __syncthreads();
#pragma unroll
    for (int i = 0; i < 32; i += 8) {
        float v = tile[tx][ty + i];
        __nv_bfloat16 h = __float2bfloat16(v);
        __nv_bfloat16 l = __float2bfloat16(v - __bfloat162float(h));
        Th[(size_t)(nb + ty + i) * K + kb + tx] = h;
        Tl[(size_t)(nb + ty + i) * K + kb + tx] = l;
    }
}

// ---------------------------------------------------------------------------
// Causal depthwise conv (width 4) + SiLU.
// ---------------------------------------------------------------------------
__global__ __launch_bounds__(256)
void conv_silu_kernel(const float* __restrict__ conv_w, const float* __restrict__ conv_b)
{
    const int m = blockIdx.y;
    const int d = blockIdx.x * 256 + threadIdx.x;
    const int t = m & (SEQLEN - 1);

    float4 w = *(const float4*)(conv_w + d * 4);
    float acc = conv_b[d];
    const float* base = g_xz + (size_t)m * NXZ + d;

    if (t >= 3) {
        acc = fmaf(base[-3 * NXZ], w.x, acc);
        acc = fmaf(base[-2 * NXZ], w.y, acc);
        acc = fmaf(base[-1 * NXZ], w.z, acc);
        acc = fmaf(base[0],        w.w, acc);
    } else {
        const float wk[4] = { w.x, w.y, w.z, w.w };
#pragma unroll
        for (int k = 0; k < 4; k++) {
            int ts = t - 3 + k;
            if (ts >= 0) acc = fmaf(base[(k - 3) * NXZ], wk[k], acc);
        }
    }
    float s = acc / (1.f + expf(-acc));
    g_xc[(size_t)m * DINNER + d] = s;
}

// ---------------------------------------------------------------------------
__global__ void check_kernel(const float* __restrict__ A_log)
{
    int idx = blockIdx.x * blockDim.x + threadIdx.x;
    if (idx < DINNER * DSTATE) {
        if (A_log[idx] != A_log[idx & 15]) atomicOr(&g_nonuni, 1);
    }
}

// ---------------------------------------------------------------------------
// proj partials: slice ks covers K range [ks*512, ks*512+512).
// ---------------------------------------------------------------------------
#define PBK 64
__global__ __launch_bounds__(256)
void proj_gemm_kernel(const float* __restrict__ W_xproj)
{
    __shared__ float As[PBK][33];
    __shared__ float Ws[PBK][36];

    const int tid = threadIdx.x;
    const int m0  = blockIdx.x * 32;
    const int ks  = blockIdx.y;
    const int kb  = ks * (DINNER / KSPLIT);

    const int r  = tid & 31;
    const int tc = tid >> 5;

    float acc[4] = {0.f, 0.f, 0.f, 0.f};
    float acc32  = 0.f;

    for (int k0 = kb; k0 < kb + DINNER / KSPLIT; k0 += PBK) {
#pragma unroll
        for (int i = 0; i < 2; i++) {
            int f    = tid + i * 256;
            int row  = f >> 4;
            int col4 = f & 15;
            float4 v = *(const float4*)(g_xc + (size_t)(m0 + row) * DINNER + k0 + col4 * 4);
            As[col4 * 4 + 0][row] = v.x;
            As[col4 * 4 + 1][row] = v.y;
            As[col4 * 4 + 2][row] = v.z;
            As[col4 * 4 + 3][row] = v.w;
        }
        for (int idx = tid; idx < PBK * NPROJ; idx += 256) {
            int k = idx / NPROJ;
            int j = idx - k * NPROJ;
            Ws[k][j] = W_xproj[(size_t)(k0 + k) * NPROJ + j];
        }
        __syncthreads();

#pragma unroll 8
        for (int k = 0; k < PBK; k++) {
            float a  = As[k][r];
            float4 w = *(const float4*)(&Ws[k][tc * 4]);
            acc[0] = fmaf(a, w.x, acc[0]);
            acc[1] = fmaf(a, w.y, acc[1]);
            acc[2] = fmaf(a, w.z, acc[2]);
            acc[3] = fmaf(a, w.w, acc[3]);
            if (tc == 0) acc32 = fmaf(a, Ws[k][32], acc32);
        }
        __syncthreads();
    }

    float* prow = g_projp + ((size_t)ks * M_ROWS + m0 + r) * NPROJ;
#pragma unroll
    for (int jj = 0; jj < 4; jj++)
        prow[tc * 4 + jj] = acc[jj];
    if (tc == 0) prow[32] = acc32;
}

// ---------------------------------------------------------------------------
// Coefficients (sums the KSPLIT partials). One thread per (m, n).
// ---------------------------------------------------------------------------
__global__ __launch_bounds__(256)
void coef_kernel(const float* __restrict__ A_log)
{
    const int idx = blockIdx.x * 256 + threadIdx.x;
    const int m = idx >> 4;
    const int n = idx & 15;

    float pn = 0.f, pc = 0.f, pd = 0.f;
#pragma unroll
    for (int s = 0; s < KSPLIT; s++) {
        const float* p = g_projp + ((size_t)s * M_ROWS + m) * NPROJ;
        pn += p[n];
        pc += p[16 + n];
        pd += p[32];
    }
    float delta = (pd > 20.f) ? pd : log1pf(expf(pd));

    float An = -expf(A_log[n]);
    g_coef[(size_t)m * 48 + n]      = expf(delta * An);
    g_coef[(size_t)m * 48 + 16 + n] = delta * pn;
    g_coef[(size_t)m * 48 + 32 + n] = pc;
    if (n == 0) g_delta[m] = delta;
}

// ---------------------------------------------------------------------------
__global__ void chunkprod_kernel()
{
    const int c = blockIdx.x;
    const int n = threadIdx.x;
    const int mbase = c * CHUNK;
    float P = 1.f;
#pragma unroll
    for (int tt = 0; tt < CHUNK; tt++) {
        const int m = mbase + tt;
        P *= g_coef[(size_t)m * 48 + n];
        g_wpre[(size_t)m * DSTATE + n] = g_coef[(size_t)m * 48 + 32 + n] * P;
    }
    g_Ac[c * DSTATE + n] = P;
}

// ---------------------------------------------------------------------------
__global__ __launch_bounds__(32)
void scan_local_kernel()
{
    const int lane  = threadIdx.x;
    const int c     = blockIdx.x >> 6;
    const int d     = (blockIdx.x & 63) * 32 + lane;
    const int mbase = c * CHUNK;

    __shared__ float4 sc[CHUNK][12];
    __shared__ float  sx[CHUNK][32];

    {
        const float4* src = (const float4*)(g_coef + (size_t)mbase * 48);
        float4* dst = (float4*)sc;
#pragma unroll
        for (int i = 0; i < 12; i++)
            dst[lane + i * 32] = src[lane + i * 32];
#pragma unroll
        for (int i = 0; i < CHUNK; i++)
            sx[i][lane] = g_xc[(size_t)(mbase + i) * DINNER + d];
    }
    __syncwarp();

    float h[16];
#pragma unroll
    for (int n = 0; n < 16; n++) h[n] = 0.f;

#pragma unroll 8
    for (int tt = 0; tt < CHUNK; tt++) {
        const float x = sx[tt][lane];
        float y = 0.f;
#pragma unroll
        for (int q = 0; q < 4; q++) {
            float4 a4 = sc[tt][q];
            float4 b4 = sc[tt][4 + q];
            float4 c4 = sc[tt][8 + q];
            h[4*q+0] = fmaf(a4.x, h[4*q+0], b4.x * x); y = fmaf(h[4*q+0], c4.x, y);
            h[4*q+1] = fmaf(a4.y, h[4*q+1], b4.y * x); y = fmaf(h[4*q+1], c4.y, y);
            h[4*q+2] = fmaf(a4.z, h[4*q+2], b4.z * x); y = fmaf(h[4*q+2], c4.z, y);
            h[4*q+3] = fmaf(a4.w, h[4*q+3], b4.w * x); y = fmaf(h[4*q+3], c4.w, y);
        }
        g_y[(size_t)(mbase + tt) * DINNER + d] = y;
    }

    float* hl = g_hloc + ((size_t)c * DINNER + d) * DSTATE;
#pragma unroll
    for (int q = 0; q < 4; q++)
        *(float4*)(hl + 4 * q) = make_float4(h[4*q], h[4*q+1], h[4*q+2], h[4*q+3]);
}

// ---------------------------------------------------------------------------
__global__ __launch_bounds__(256)
void carry_kernel()
{
    const int idx = blockIdx.x * 256 + threadIdx.x;
    const int b = idx >> 15;
    const int d = (idx >> 4) & (DINNER - 1);
    const int n = idx & 15;

    float h = 0.f;
    for (int cl = 0; cl < NCH_B; cl++) {
        const int c = b * NCH_B + cl;
        const size_t off = ((size_t)c * DINNER + d) * DSTATE + n;
        g_hstart[off] = h;
        h = fmaf(g_Ac[c * DSTATE + n], h, g_hloc[off]);
    }
}

// ---------------------------------------------------------------------------
// Combine + gated epilogue, FUSED with y hi/lo bf16 split (writes yh/yl).
// ---------------------------------------------------------------------------
__global__ __launch_bounds__(32)
void finish_kernel(const float* __restrict__ D_param)
{
    const int lane  = threadIdx.x;
    const int c     = blockIdx.x >> 6;
    const int d     = (blockIdx.x & 63) * 32 + lane;
    const int mbase = c * CHUNK;

    __shared__ float4 sw[CHUNK * 4];
    {
        const float4* src = (const float4*)(g_wpre + (size_t)mbase * DSTATE);
#pragma unroll
        for (int i = 0; i < 4; i++)
            sw[lane + i * 32] = src[lane + i * 32];
    }

    float hs[16];
    {
        const float* hp = g_hstart + ((size_t)c * DINNER + d) * DSTATE;
#pragma unroll
        for (int q = 0; q < 4; q++) {
            float4 v = *(const float4*)(hp + 4 * q);
            hs[4*q] = v.x; hs[4*q+1] = v.y; hs[4*q+2] = v.z; hs[4*q+3] = v.w;
        }
    }
    const float Dp = D_param[d];
    __syncwarp();

#pragma unroll 8
    for (int tt = 0; tt < CHUNK; tt++) {
        const int m = mbase + tt;
        float y = g_y[(size_t)m * DINNER + d];
#pragma unroll
        for (int q = 0; q < 4; q++) {
            float4 w4 = sw[tt * 4 + q];
            y = fmaf(w4.x, hs[4*q+0], y);
            y = fmaf(w4.y, hs[4*q+1], y);
            y = fmaf(w4.z, hs[4*q+2], y);
            y = fmaf(w4.w, hs[4*q+3], y);
        }
        const float x = g_xc[(size_t)m * DINNER + d];
        const float z = g_xz[(size_t)m * NXZ + DINNER + d];
        const float sz = z / (1.f + expf(-z));
        const float yv = (y + x * Dp) * sz;
        __nv_bfloat16 hh = __float2bfloat16(yv);
        __nv_bfloat16 ll = __float2bfloat16(yv - __bfloat162float(hh));
        g_yh[(size_t)m * DINNER + d] = hh;
        g_yl[(size_t)m * DINNER + d] = ll;
    }
}

// ---------------------------------------------------------------------------
// Fallback: full sequential scan (only if A non-uniform). Writes yh/yl.
// ---------------------------------------------------------------------------
__global__ __launch_bounds__(32)
void scan_fallback_kernel(const float* __restrict__ D_param, const float* __restrict__ A_log)
{
    if (*((volatile int*)&g_nonuni) == 0) return;

    const int lane  = threadIdx.x;
    const int b     = blockIdx.x >> 6;
    const int d     = (blockIdx.x & 63) * 32 + lane;
    const int mbase = b * SEQLEN;

    const float Dp = D_param[d];
    float Aloc[16];
#pragma unroll
    for (int n = 0; n < 16; n++) Aloc[n] = -expf(A_log[d * 16 + n]);

    float h[16];
#pragma unroll
    for (int n = 0; n < 16; n++) h[n] = 0.f;

    __shared__ float4 sc[32][12];

    for (int t0 = 0; t0 < SEQLEN; t0 += 32) {
        __syncthreads();
        const float4* src = (const float4*)(g_coef + (size_t)(mbase + t0) * 48);
        float4* dst = (float4*)sc;
#pragma unroll
        for (int i = 0; i < 12; i++)
            dst[lane + i * 32] = src[lane + i * 32];
        __syncthreads();

        for (int tt = 0; tt < 32; tt++) {
            const int m = mbase + t0 + tt;
            const float x = g_xc[(size_t)m * DINNER + d];
            const float dlt = g_delta[m];
            float y = 0.f;
#pragma unroll
            for (int q = 0; q < 4; q++) {
                float4 b4 = sc[tt][4 + q];
                float4 c4 = sc[tt][8 + q];
                float a0 = expf(dlt * Aloc[4*q+0]);
                float a1 = expf(dlt * Aloc[4*q+1]);
                float a2 = expf(dlt * Aloc[4*q+2]);
                float a3 = expf(dlt * Aloc[4*q+3]);
                h[4*q+0] = fmaf(a0, h[4*q+0], b4.x * x); y = fmaf(h[4*q+0], c4.x, y);
                h[4*q+1] = fmaf(a1, h[4*q+1], b4.y * x); y = fmaf(h[4*q+1], c4.y, y);
                h[4*q+2] = fmaf(a2, h[4*q+2], b4.z * x); y = fmaf(h[4*q+2], c4.z, y);
                h[4*q+3] = fmaf(a3, h[4*q+3], b4.w * x); y = fmaf(h[4*q+3], c4.w, y);
            }
            float z  = g_xz[(size_t)m * NXZ + DINNER + d];
            float sz = z / (1.f + expf(-z));
            const float yv = (y + x * Dp) * sz;
            __nv_bfloat16 hh = __float2bfloat16(yv);
            __nv_bfloat16 ll = __float2bfloat16(yv - __bfloat162float(hh));
            g_yh[(size_t)m * DINNER + d] = hh;
            g_yl[(size_t)m * DINNER + d] = ll;
        }
    }
}

// ---------------------------------------------------------------------------
extern "C" void kernel_launch(void* const* d_in, const int* in_sizes, int n_in,
                              void* d_out, int out_size)
{
    const float* x       = (const float*)d_in[0];
    const float* W_in    = (const float*)d_in[1];
    const float* b_in    = (const float*)d_in[2];
    const float* conv_w  = (const float*)d_in[3];
    const float* conv_b  = (const float*)d_in[4];
    const float* W_xproj = (const float*)d_in[5];
    const float* A_log   = (const float*)d_in[6];
    const float* D_param = (const float*)d_in[7];
    const float* W_out   = (const float*)d_in[8];
    const float* b_out   = (const float*)d_in[9];
    float* out = (float*)d_out;

    float *p_xz;
    void  *p_flag;
    __nv_bfloat16 *p_a1h, *p_a1l, *p_w1h, *p_w1l, *p_yh, *p_yl, *p_w2h, *p_w2l;
    cudaGetSymbolAddress((void**)&p_xz,  g_xz);
    cudaGetSymbolAddress(&p_flag, g_nonuni);
    cudaGetSymbolAddress((void**)&p_a1h, g_a1h);
    cudaGetSymbolAddress((void**)&p_a1l, g_a1l);
    cudaGetSymbolAddress((void**)&p_w1h, g_w1h);
    cudaGetSymbolAddress((void**)&p_w1l, g_w1l);
    cudaGetSymbolAddress((void**)&p_yh,  g_yh);
    cudaGetSymbolAddress((void**)&p_yl,  g_yl);
    cudaGetSymbolAddress((void**)&p_w2h, g_w2h);
    cudaGetSymbolAddress((void**)&p_w2l, g_w2l);

    cudaFuncSetAttribute(mm_tc_kernel, cudaFuncAttributeMaxDynamicSharedMemorySize,
                         MM_DSMEM);

    // 0) operand conversions
    split_kernel<<<(M_ROWS * DMODEL / 4 + 255) / 256, 256>>>(x, p_a1h, p_a1l,
                                                             M_ROWS * DMODEL / 4);
    transpose_split_kernel<<<dim3(NXZ / 32, DMODEL / 32), 256>>>(W_in, p_w1h, p_w1l,
                                                                 DMODEL, NXZ);
    transpose_split_kernel<<<dim3(DMODEL / 32, DINNER / 32), 256>>>(W_out, p_w2h, p_w2l,
                                                                    DINNER, DMODEL);
    // 1) xz = x @ W_in + b_in  (HMMA split-bf16, cp.async pipelined)
    mm_tc_kernel<<<dim3(NXZ / 128, M_ROWS / 128), 256, MM_DSMEM>>>(
        p_a1h, p_a1l, p_w1h, p_w1l, b_in, p_xz, M_ROWS, NXZ, DMODEL);
    // 2) conv + silu -> g_xc
    conv_silu_kernel<<<dim3(DINNER / 256, M_ROWS), 256>>>(conv_w, conv_b);
    // 3) uniformity check
    cudaMemsetAsync(p_flag, 0, sizeof(int));
    check_kernel<<<(DINNER * DSTATE + 255) / 256, 256>>>(A_log);
    // 4) projection (split-K) + coefficients
    proj_gemm_kernel<<<dim3(M_ROWS / 32, KSPLIT), 256>>>(W_xproj);
    coef_kernel<<<(M_ROWS * DSTATE) / 256, 256>>>(A_log);
    // 5) chunk prefix products
    chunkprod_kernel<<<NCHUNK, DSTATE>>>();
    // 6) local scans
    scan_local_kernel<<<NCHUNK * (DINNER / 32), 32>>>();
    // 7) carry scan
    carry_kernel<<<(BATCH * DINNER * DSTATE) / 256, 256>>>();
    // 8) combine + gated epilogue + fused y split -> yh/yl
    finish_kernel<<<NCHUNK * (DINNER / 32), 32>>>(D_param);
    // 9) fallback (early-exits when A uniform)
    scan_fallback_kernel<<<128, 32>>>(D_param, A_log);
    // 10) out = y @ W_out + b_out (HMMA pipelined)
    mm_tc_kernel<<<dim3(DMODEL / 128, M_ROWS / 128), 256, MM_DSMEM>>>(
        p_yh, p_yl, p_w2h, p_w2l, b_out, out, M_ROWS, DMODEL, DINNER);
}

// round 15
// speedup vs baseline: 1.2235x; 1.0316x over previous
#include <cuda_runtime.h>
#include <cuda_bf16.h>
#include <math.h>
#include <stdint.h>

#define BATCH   2
#define SEQLEN  2048
#define DMODEL  1024
#define DINNER  2048
#define DSTATE  16
#define DCONV   4
#define M_ROWS  (BATCH * SEQLEN)   // 4096
#define NXZ     (2 * DINNER)       // 4096
#define CHUNK   32
#define NCHUNK  (M_ROWS / CHUNK)   // 128
#define NCH_B   (SEQLEN / CHUNK)   // 64
#define NPROJ   33
#define KSPLIT  8

// ---------------- scratch (static device arrays) ----------------
__device__ float g_xz[M_ROWS * NXZ];           // 64 MB
__device__ float g_xc[M_ROWS * DINNER];        // 32 MB
__device__ float g_y [M_ROWS * DINNER];        // y_local (scan) 32 MB
__device__ float g_projp[KSPLIT * M_ROWS * NPROJ];
__device__ float g_coef[M_ROWS * 48];
__device__ float g_delta[M_ROWS];
__device__ float g_wpre[M_ROWS * DSTATE];
__device__ float g_Ac[NCHUNK * DSTATE];
__device__ float g_hloc [NCHUNK * DINNER * DSTATE];
__device__ float g_hstart[NCHUNK * DINNER * DSTATE];
__device__ int   g_nonuni;

// split-bf16 operands
__device__ __nv_bfloat16 g_a1h[M_ROWS * DMODEL], g_a1l[M_ROWS * DMODEL];   // x hi/lo
__device__ __nv_bfloat16 g_w1h[NXZ * DMODEL],    g_w1l[NXZ * DMODEL];      // W_in^T [N][K]
__device__ __nv_bfloat16 g_yh [M_ROWS * DINNER], g_yl [M_ROWS * DINNER];   // y hi/lo
__device__ __nv_bfloat16 g_w2h[DMODEL * DINNER], g_w2l[DMODEL * DINNER];   // W_out^T [N][K]

// ---------------- helpers ----------------
__device__ __forceinline__ uint32_t smem_to_u32(const void* p) {
    uint32_t a;
    asm("{ .reg .u64 t; cvta.to.shared.u64 t, %1; cvt.u32.u64 %0, t; }" : "=r"(a) : "l"(p));
    return a;
}

__device__ __forceinline__ void ldsm_x4(uint32_t& r0, uint32_t& r1, uint32_t& r2, uint32_t& r3,
                                        uint32_t addr) {
    asm volatile("ldmatrix.sync.aligned.m8n8.x4.shared.b16 {%0,%1,%2,%3}, [%4];"
                 : "=r"(r0), "=r"(r1), "=r"(r2), "=r"(r3) : "r"(addr));
}

__device__ __forceinline__ void mma_bf16(float& d0, float& d1, float& d2, float& d3,
                                         uint32_t a0, uint32_t a1, uint32_t a2, uint32_t a3,
                                         uint32_t b0, uint32_t b1) {
    asm volatile("mma.sync.aligned.m16n8k16.row.col.f32.bf16.bf16.f32 "
                 "{%0,%1,%2,%3}, {%4,%5,%6,%7}, {%8,%9}, {%0,%1,%2,%3};"
                 : "+f"(d0), "+f"(d1), "+f"(d2), "+f"(d3)
                 : "r"(a0), "r"(a1), "r"(a2), "r"(a3), "r"(b0), "r"(b1));
}

__device__ __forceinline__ void cp_async16(uint32_t dst, const void* src) {
    asm volatile("cp.async.cg.shared.global [%0], [%1], 16;" :: "r"(dst), "l"(src));
}
#define CP_COMMIT() asm volatile("cp.async.commit_group;" ::: "memory")
#define CP_WAIT1()  asm volatile("cp.async.wait_group 1;" ::: "memory")

// ---------------------------------------------------------------------------
// Split-bf16 tensor-core GEMM via mma.sync (HMMA), cp.async double-buffered.
// PROVEN SHAPE: 128x128 CTA tile, 256 threads, 8 warps (4m x 2n),
// warp tile 32x64 (2 m16 x 8 n8), KTILE=32, two 40KB stages -> 2 CTAs/SM.
// 3 passes: Ah*Bh + Ah*Bl + Al*Bh (fp32 accum). Rows padded to 40 bf16 (80B):
// ldmatrix 8-row phases hit banks {0,20,8,28,16,4,24,12} — conflict-free.
// ---------------------------------------------------------------------------
#define KTILE 32
#define ROWP  40                      // padded row length in bf16 (80 bytes)
#define MATB  (128 * ROWP * 2)        // 10240 bytes per matrix
#define STAGEB (4 * MATB)             // 40960 bytes per stage
#define MM_DSMEM (2 * STAGEB)         // 81920

__global__ __launch_bounds__(256)
void mm_tc_kernel(const __nv_bfloat16* __restrict__ Ah, const __nv_bfloat16* __restrict__ Al,
                  const __nv_bfloat16* __restrict__ Bh, const __nv_bfloat16* __restrict__ Bl,
                  const float* __restrict__ bias, float* __restrict__ C,
                  int M, int N, int K)
{
    extern __shared__ __align__(16) char dynsm[];
    const uint32_t sbase = smem_to_u32(dynsm);

    const int tid  = threadIdx.x;
    const int wid  = tid >> 5;
    const int lane = tid & 31;
    const int n0 = blockIdx.x * 128;
    const int m0 = blockIdx.y * 128;

    const int wm = wid >> 1;        // 0..3 -> m offset wm*32
    const int wn = wid & 1;         // 0..1 -> n offset wn*64

    float acc[2][8][4];             // [mt][nt][frag]
#pragma unroll
    for (int i = 0; i < 2; i++)
#pragma unroll
        for (int j = 0; j < 8; j++)
#pragma unroll
            for (int q = 0; q < 4; q++) acc[i][j][q] = 0.f;

    const uint32_t a_row  = (uint32_t)(wm * 32 + (lane & 15));
    const uint32_t a_coff = (uint32_t)((lane >> 4) * 16);
    const uint32_t b_row  = (uint32_t)(wn * 64 + (lane & 7) + ((lane >> 4) << 3));
    const uint32_t b_koff = (uint32_t)(((lane >> 3) & 1) * 16);

    const int nk = K / KTILE;

    // ---- prologue: async-load k-tile 0 into stage 0 ----
#pragma unroll
    for (int j = 0; j < 8; j++) {
        int i    = tid + j * 256;
        int mId  = i >> 9;
        int w    = i & 511;
        int row  = w >> 2;
        int c4   = w & 3;
        const __nv_bfloat16* src =
            (mId == 0) ? Ah : (mId == 1) ? Al : (mId == 2) ? Bh : Bl;
        const int r0 = (mId < 2) ? m0 : n0;
        cp_async16(sbase + mId * MATB + (uint32_t)(row * 80 + c4 * 16),
                   src + (size_t)(r0 + row) * K + c4 * 8);
    }
    CP_COMMIT();

    for (int kt = 0; kt < nk; kt++) {
        const int cur = kt & 1;
        if (kt + 1 < nk) {
            const int k1 = (kt + 1) * KTILE;
            const uint32_t stoff = (uint32_t)((cur ^ 1) * STAGEB);
#pragma unroll
            for (int j = 0; j < 8; j++) {
                int i    = tid + j * 256;
                int mId  = i >> 9;
                int w    = i & 511;
                int row  = w >> 2;
                int c4   = w & 3;
                const __nv_bfloat16* src =
                    (mId == 0) ? Ah : (mId == 1) ? Al : (mId == 2) ? Bh : Bl;
                const int r0 = (mId < 2) ? m0 : n0;
                cp_async16(sbase + stoff + mId * MATB + (uint32_t)(row * 80 + c4 * 16),
                           src + (size_t)(r0 + row) * K + k1 + c4 * 8);
            }
        }
        CP_COMMIT();
        CP_WAIT1();
        __syncthreads();

        const uint32_t sb = sbase + (uint32_t)(cur * STAGEB);
#pragma unroll
        for (int kk = 0; kk < 2; kk++) {
            uint32_t ah[2][4], al[2][4];
#pragma unroll
            for (int mt = 0; mt < 2; mt++) {
                uint32_t off = (a_row + mt * 16) * 80 + kk * 32 + a_coff;
                ldsm_x4(ah[mt][0], ah[mt][1], ah[mt][2], ah[mt][3], sb + off);
                ldsm_x4(al[mt][0], al[mt][1], al[mt][2], al[mt][3], sb + MATB + off);
            }
            uint32_t bh[8][2], bl[8][2];
#pragma unroll
            for (int np = 0; np < 4; np++) {
                uint32_t off = (b_row + np * 16) * 80 + kk * 32 + b_koff;
                uint32_t r0, r1, r2, r3;
                ldsm_x4(r0, r1, r2, r3, sb + 2 * MATB + off);
                bh[np*2][0] = r0; bh[np*2][1] = r1; bh[np*2+1][0] = r2; bh[np*2+1][1] = r3;
                ldsm_x4(r0, r1, r2, r3, sb + 3 * MATB + off);
                bl[np*2][0] = r0; bl[np*2][1] = r1; bl[np*2+1][0] = r2; bl[np*2+1][1] = r3;
            }
#pragma unroll
            for (int mt = 0; mt < 2; mt++)
#pragma unroll
                for (int nt = 0; nt < 8; nt++) {
                    float* d = acc[mt][nt];
                    mma_bf16(d[0], d[1], d[2], d[3],
                             ah[mt][0], ah[mt][1], ah[mt][2], ah[mt][3],
                             bh[nt][0], bh[nt][1]);
                    mma_bf16(d[0], d[1], d[2], d[3],
                             ah[mt][0], ah[mt][1], ah[mt][2], ah[mt][3],
                             bl[nt][0], bl[nt][1]);
                    mma_bf16(d[0], d[1], d[2], d[3],
                             al[mt][0], al[mt][1], al[mt][2], al[mt][3],
                             bh[nt][0], bh[nt][1]);
                }
        }
        __syncthreads();
    }

    // ---- epilogue
    const int rbase = m0 + wm * 32 + (lane >> 2);
    const int cbase = n0 + wn * 64 + (lane & 3) * 2;
#pragma unroll
    for (int mt = 0; mt < 2; mt++) {
#pragma unroll
        for (int nt = 0; nt < 8; nt++) {
            int r = rbase + mt * 16;
            int c = cbase + nt * 8;
            float b0 = bias[c], b1 = bias[c + 1];
            float2 o0 = { acc[mt][nt][0] + b0, acc[mt][nt][1] + b1 };
            float2 o1 = { acc[mt][nt][2] + b0, acc[mt][nt][3] + b1 };
            *(float2*)(C + (size_t)r * N + c)       = o0;
            *(float2*)(C + (size_t)(r + 8) * N + c) = o1;
        }
    }
}

// ---------------------------------------------------------------------------
// fp32 -> (hi, lo) bf16 split, elementwise, vectorized.
// ---------------------------------------------------------------------------
__global__ __launch_bounds__(256)
void split_kernel(const float* __restrict__ src, __nv_bfloat16* __restrict__ h,
                  __nv_bfloat16* __restrict__ l, int n4)
{
    int i = blockIdx.x * 256 + threadIdx.x;
    if (i >= n4) return;
    float4 v = ((const float4*)src)[i];
    float f[4] = { v.x, v.y, v.z, v.w };
    __nv_bfloat16 hh[4], ll[4];
#pragma unroll
    for (int j = 0; j < 4; j++) {
        hh[j] = __float2bfloat16(f[j]);
        ll[j] = __float2bfloat16(f[j] - __bfloat162float(hh[j]));
    }
    ((ushort4*)h)[i] = *(ushort4*)hh;
    ((ushort4*)l)[i] = *(ushort4*)ll;
}

// ---------------------------------------------------------------------------
// W[K][N] -> T[N][K] transpose with hi/lo bf16 split. 32x32 tiles.
// ---------------------------------------------------------------------------
__global__ __launch_bounds__(256)
void transpose_split_kernel(const float* __restrict__ W, __nv_bfloat16* __restrict__ Th,
                            __nv_bfloat16* __restrict__ Tl, int K, int N)
{
    __shared__ float tile[32][33];
    const int nb = blockIdx.x * 32;
    const int kb = blockIdx.y * 32;
    const int tx = threadIdx.x & 31;
    const int ty = threadIdx.x >> 5;
#pragma unroll
    for (int i = 0; i < 32; i += 8)
        tile[ty + i][tx] = W[(size_t)(kb + ty + i) * N + nb + tx];
    __syncthreads();
#pragma unroll
    for (int i = 0; i < 32; i += 8) {
        float v = tile[tx][ty + i];
        __nv_bfloat16 h = __float2bfloat16(v);
        __nv_bfloat16 l = __float2bfloat16(v - __bfloat162float(h));
        Th[(size_t)(nb + ty + i) * K + kb + tx] = h;
        Tl[(size_t)(nb + ty + i) * K + kb + tx] = l;
    }
}

// ---------------------------------------------------------------------------
// Causal depthwise conv (width 4) + SiLU.
// ---------------------------------------------------------------------------
__global__ __launch_bounds__(256)
void conv_silu_kernel(const float* __restrict__ conv_w, const float* __restrict__ conv_b)
{
    const int m = blockIdx.y;
    const int d = blockIdx.x * 256 + threadIdx.x;
    const int t = m & (SEQLEN - 1);

    float4 w = *(const float4*)(conv_w + d * 4);
    float acc = conv_b[d];
    const float* base = g_xz + (size_t)m * NXZ + d;

    if (t >= 3) {
        acc = fmaf(base[-3 * NXZ], w.x, acc);
        acc = fmaf(base[-2 * NXZ], w.y, acc);
        acc = fmaf(base[-1 * NXZ], w.z, acc);
        acc = fmaf(base[0],        w.w, acc);
    } else {
        const float wk[4] = { w.x, w.y, w.z, w.w };
#pragma unroll
        for (int k = 0; k < 4; k++) {
            int ts = t - 3 + k;
            if (ts >= 0) acc = fmaf(base[(k - 3) * NXZ], wk[k], acc);
        }
    }
    float s = acc / (1.f + expf(-acc));
    g_xc[(size_t)m * DINNER + d] = s;
}

// ---------------------------------------------------------------------------
__global__ void check_kernel(const float* __restrict__ A_log)
{
    int idx = blockIdx.x * blockDim.x + threadIdx.x;
    if (idx < DINNER * DSTATE) {
        if (A_log[idx] != A_log[idx & 15]) atomicOr(&g_nonuni, 1);
    }
}

// ---------------------------------------------------------------------------
// proj partials: slice ks covers K range [ks*256, ks*256+256).
// ---------------------------------------------------------------------------
#define PBK 64
__global__ __launch_bounds__(256)
void proj_gemm_kernel(const float* __restrict__ W_xproj)
{
    __shared__ float As[PBK][33];
    __shared__ float Ws[PBK][36];

    const int tid = threadIdx.x;
    const int m0  = blockIdx.x * 32;
    const int ks  = blockIdx.y;
    const int kb  = ks * (DINNER / KSPLIT);

    const int r  = tid & 31;
    const int tc = tid >> 5;

    float acc[4] = {0.f, 0.f, 0.f, 0.f};
    float acc32  = 0.f;

    for (int k0 = kb; k0 < kb + DINNER / KSPLIT; k0 += PBK) {
#pragma unroll
        for (int i = 0; i < 2; i++) {
            int f    = tid + i * 256;
            int row  = f >> 4;
            int col4 = f & 15;
            float4 v = *(const float4*)(g_xc + (size_t)(m0 + row) * DINNER + k0 + col4 * 4);
            As[col4 * 4 + 0][row] = v.x;
            As[col4 * 4 + 1][row] = v.y;
            As[col4 * 4 + 2][row] = v.z;
            As[col4 * 4 + 3][row] = v.w;
        }
        for (int idx = tid; idx < PBK * NPROJ; idx += 256) {
            int k = idx / NPROJ;
            int j = idx - k * NPROJ;
            Ws[k][j] = W_xproj[(size_t)(k0 + k) * NPROJ + j];
        }
        __syncthreads();

#pragma unroll 8
        for (int k = 0; k < PBK; k++) {
            float a  = As[k][r];
            float4 w = *(const float4*)(&Ws[k][tc * 4]);
            acc[0] = fmaf(a, w.x, acc[0]);
            acc[1] = fmaf(a, w.y, acc[1]);
            acc[2] = fmaf(a, w.z, acc[2]);
            acc[3] = fmaf(a, w.w, acc[3]);
            if (tc == 0) acc32 = fmaf(a, Ws[k][32], acc32);
        }
        __syncthreads();
    }

    float* prow = g_projp + ((size_t)ks * M_ROWS + m0 + r) * NPROJ;
#pragma unroll
    for (int jj = 0; jj < 4; jj++)
        prow[tc * 4 + jj] = acc[jj];
    if (tc == 0) prow[32] = acc32;
}

// ---------------------------------------------------------------------------
// Coefficients (sums the KSPLIT partials). One thread per (m, n).
// ---------------------------------------------------------------------------
__global__ __launch_bounds__(256)
void coef_kernel(const float* __restrict__ A_log)
{
    const int idx = blockIdx.x * 256 + threadIdx.x;
    const int m = idx >> 4;
    const int n = idx & 15;

    float pn = 0.f, pc = 0.f, pd = 0.f;
#pragma unroll
    for (int s = 0; s < KSPLIT; s++) {
        const float* p = g_projp + ((size_t)s * M_ROWS + m) * NPROJ;
        pn += p[n];
        pc += p[16 + n];
        pd += p[32];
    }
    float delta = (pd > 20.f) ? pd : log1pf(expf(pd));

    float An = -expf(A_log[n]);
    g_coef[(size_t)m * 48 + n]      = expf(delta * An);
    g_coef[(size_t)m * 48 + 16 + n] = delta * pn;
    g_coef[(size_t)m * 48 + 32 + n] = pc;
    if (n == 0) g_delta[m] = delta;
}

// ---------------------------------------------------------------------------
// Phase 1: local scans. 128 threads = 4 warps, one chunk, 4 d-groups of 32.
// Coef tile loaded ONCE per block (shared by 4 warps). dg==0 blocks also
// compute the per-chunk prefix products (wpre/Ac) from the staged coefs.
// grid = NCHUNK * 16
// ---------------------------------------------------------------------------
__global__ __launch_bounds__(128)
void scan_local_kernel()
{
    const int tid  = threadIdx.x;
    const int lane = tid & 31;
    const int wd   = tid >> 5;                  // warp 0..3
    const int c    = blockIdx.x >> 4;           // chunk
    const int dg   = blockIdx.x & 15;           // d-group of 128
    const int d    = dg * 128 + wd * 32 + lane;
    const int mbase = c * CHUNK;

    __shared__ float4 sc[CHUNK][12];            // 48 floats per timestep
    __shared__ float  sx[CHUNK][128];

    {
        const float4* src = (const float4*)(g_coef + (size_t)mbase * 48);
        float4* dst = (float4*)sc;
#pragma unroll
        for (int i = 0; i < 3; i++)
            dst[tid + i * 128] = src[tid + i * 128];
#pragma unroll
        for (int i = 0; i < CHUNK; i++)
            sx[i][wd * 32 + lane] = g_xc[(size_t)(mbase + i) * DINNER + d];
    }
    __syncthreads();

    float h[16];
#pragma unroll
    for (int n = 0; n < 16; n++) h[n] = 0.f;

#pragma unroll 8
    for (int tt = 0; tt < CHUNK; tt++) {
        const float x = sx[tt][wd * 32 + lane];
        float y = 0.f;
#pragma unroll
        for (int q = 0; q < 4; q++) {
            float4 a4 = sc[tt][q];
            float4 b4 = sc[tt][4 + q];
            float4 c4 = sc[tt][8 + q];
            h[4*q+0] = fmaf(a4.x, h[4*q+0], b4.x * x); y = fmaf(h[4*q+0], c4.x, y);
            h[4*q+1] = fmaf(a4.y, h[4*q+1], b4.y * x); y = fmaf(h[4*q+1], c4.y, y);
            h[4*q+2] = fmaf(a4.z, h[4*q+2], b4.z * x); y = fmaf(h[4*q+2], c4.z, y);
            h[4*q+3] = fmaf(a4.w, h[4*q+3], b4.w * x); y = fmaf(h[4*q+3], c4.w, y);
        }
        g_y[(size_t)(mbase + tt) * DINNER + d] = y;
    }

    float* hl = g_hloc + ((size_t)c * DINNER + d) * DSTATE;
#pragma unroll
    for (int q = 0; q < 4; q++)
        *(float4*)(hl + 4 * q) = make_float4(h[4*q], h[4*q+1], h[4*q+2], h[4*q+3]);

    // chunk prefix products (dA running product; wpre = C * Pref), one block/chunk
    if (dg == 0 && tid < 16) {
        const float* scf = (const float*)sc;
        float P = 1.f;
#pragma unroll
        for (int tt = 0; tt < CHUNK; tt++) {
            P *= scf[tt * 48 + tid];
            g_wpre[(size_t)(mbase + tt) * DSTATE + tid] = scf[tt * 48 + 32 + tid] * P;
        }
        g_Ac[c * DSTATE + tid] = P;
    }
}

// ---------------------------------------------------------------------------
__global__ __launch_bounds__(256)
void carry_kernel()
{
    const int idx = blockIdx.x * 256 + threadIdx.x;
    const int b = idx >> 15;
    const int d = (idx >> 4) & (DINNER - 1);
    const int n = idx & 15;

    float h = 0.f;
    for (int cl = 0; cl < NCH_B; cl++) {
        const int c = b * NCH_B + cl;
        const size_t off = ((size_t)c * DINNER + d) * DSTATE + n;
        g_hstart[off] = h;
        h = fmaf(g_Ac[c * DSTATE + n], h, g_hloc[off]);
    }
}

// ---------------------------------------------------------------------------
// Phase 3: combine + gated epilogue + fused y hi/lo split. 128 threads,
// 4 warps share one smem load of the chunk's w-vectors. grid = NCHUNK * 16.
// ---------------------------------------------------------------------------
__global__ __launch_bounds__(128)
void finish_kernel(const float* __restrict__ D_param)
{
    const int tid  = threadIdx.x;
    const int lane = tid & 31;
    const int wd   = tid >> 5;
    const int c    = blockIdx.x >> 4;
    const int dg   = blockIdx.x & 15;
    const int d    = dg * 128 + wd * 32 + lane;
    const int mbase = c * CHUNK;

    __shared__ float4 sw[CHUNK * 4];            // 32 timesteps x 16 floats
    {
        const float4* src = (const float4*)(g_wpre + (size_t)mbase * DSTATE);
        sw[tid] = src[tid];                     // 128 float4 exactly
    }

    float hs[16];
    {
        const float* hp = g_hstart + ((size_t)c * DINNER + d) * DSTATE;
#pragma unroll
        for (int q = 0; q < 4; q++) {
            float4 v = *(const float4*)(hp + 4 * q);
            hs[4*q] = v.x; hs[4*q+1] = v.y; hs[4*q+2] = v.z; hs[4*q+3] = v.w;
        }
    }
    const float Dp = D_param[d];
    __syncthreads();

#pragma unroll 8
    for (int tt = 0; tt < CHUNK; tt++) {
        const int m = mbase + tt;
        float y = g_y[(size_t)m * DINNER + d];
#pragma unroll
        for (int q = 0; q < 4; q++) {
            float4 w4 = sw[tt * 4 + q];
            y = fmaf(w4.x, hs[4*q+0], y);
            y = fmaf(w4.y, hs[4*q+1], y);
            y = fmaf(w4.z, hs[4*q+2], y);
            y = fmaf(w4.w, hs[4*q+3], y);
        }
        const float x = g_xc[(size_t)m * DINNER + d];
        const float z = g_xz[(size_t)m * NXZ + DINNER + d];
        const float sz = z / (1.f + expf(-z));
        const float yv = (y + x * Dp) * sz;
        __nv_bfloat16 hh = __float2bfloat16(yv);
        __nv_bfloat16 ll = __float2bfloat16(yv - __bfloat162float(hh));
        g_yh[(size_t)m * DINNER + d] = hh;
        g_yl[(size_t)m * DINNER + d] = ll;
    }
}

// ---------------------------------------------------------------------------
// Fallback: full sequential scan (only if A non-uniform). Writes yh/yl.
// ---------------------------------------------------------------------------
__global__ __launch_bounds__(32)
void scan_fallback_kernel(const float* __restrict__ D_param, const float* __restrict__ A_log)
{
    if (*((volatile int*)&g_nonuni) == 0) return;

    const int lane  = threadIdx.x;
    const int b     = blockIdx.x >> 6;
    const int d     = (blockIdx.x & 63) * 32 + lane;
    const int mbase = b * SEQLEN;

    const float Dp = D_param[d];
    float Aloc[16];
#pragma unroll
    for (int n = 0; n < 16; n++) Aloc[n] = -expf(A_log[d * 16 + n]);

    float h[16];
#pragma unroll
    for (int n = 0; n < 16; n++) h[n] = 0.f;

    __shared__ float4 sc[32][12];

    for (int t0 = 0; t0 < SEQLEN; t0 += 32) {
        __syncthreads();
        const float4* src = (const float4*)(g_coef + (size_t)(mbase + t0) * 48);
        float4* dst = (float4*)sc;
#pragma unroll
        for (int i = 0; i < 12; i++)
            dst[lane + i * 32] = src[lane + i * 32];
        __syncthreads();

        for (int tt = 0; tt < 32; tt++) {
            const int m = mbase + t0 + tt;
            const float x = g_xc[(size_t)m * DINNER + d];
            const float dlt = g_delta[m];
            float y = 0.f;
#pragma unroll
            for (int q = 0; q < 4; q++) {
                float4 b4 = sc[tt][4 + q];
                float4 c4 = sc[tt][8 + q];
                float a0 = expf(dlt * Aloc[4*q+0]);
                float a1 = expf(dlt * Aloc[4*q+1]);
                float a2 = expf(dlt * Aloc[4*q+2]);
                float a3 = expf(dlt * Aloc[4*q+3]);
                h[4*q+0] = fmaf(a0, h[4*q+0], b4.x * x); y = fmaf(h[4*q+0], c4.x, y);
                h[4*q+1] = fmaf(a1, h[4*q+1], b4.y * x); y = fmaf(h[4*q+1], c4.y, y);
                h[4*q+2] = fmaf(a2, h[4*q+2], b4.z * x); y = fmaf(h[4*q+2], c4.z, y);
                h[4*q+3] = fmaf(a3, h[4*q+3], b4.w * x); y = fmaf(h[4*q+3], c4.w, y);
            }
            float z  = g_xz[(size_t)m * NXZ + DINNER + d];
            float sz = z / (1.f + expf(-z));
            const float yv = (y + x * Dp) * sz;
            __nv_bfloat16 hh = __float2bfloat16(yv);
            __nv_bfloat16 ll = __float2bfloat16(yv - __bfloat162float(hh));
            g_yh[(size_t)m * DINNER + d] = hh;
            g_yl[(size_t)m * DINNER + d] = ll;
        }
    }
}

// ---------------------------------------------------------------------------
extern "C" void kernel_launch(void* const* d_in, const int* in_sizes, int n_in,
                              void* d_out, int out_size)
{
    const float* x       = (const float*)d_in[0];
    const float* W_in    = (const float*)d_in[1];
    const float* b_in    = (const float*)d_in[2];
    const float* conv_w  = (const float*)d_in[3];
    const float* conv_b  = (const float*)d_in[4];
    const float* W_xproj = (const float*)d_in[5];
    const float* A_log   = (const float*)d_in[6];
    const float* D_param = (const float*)d_in[7];
    const float* W_out   = (const float*)d_in[8];
    const float* b_out   = (const float*)d_in[9];
    float* out = (float*)d_out;

    float *p_xz;
    void  *p_flag;
    __nv_bfloat16 *p_a1h, *p_a1l, *p_w1h, *p_w1l, *p_yh, *p_yl, *p_w2h, *p_w2l;
    cudaGetSymbolAddress((void**)&p_xz,  g_xz);
    cudaGetSymbolAddress(&p_flag, g_nonuni);
    cudaGetSymbolAddress((void**)&p_a1h, g_a1h);
    cudaGetSymbolAddress((void**)&p_a1l, g_a1l);
    cudaGetSymbolAddress((void**)&p_w1h, g_w1h);
    cudaGetSymbolAddress((void**)&p_w1l, g_w1l);
    cudaGetSymbolAddress((void**)&p_yh,  g_yh);
    cudaGetSymbolAddress((void**)&p_yl,  g_yl);
    cudaGetSymbolAddress((void**)&p_w2h, g_w2h);
    cudaGetSymbolAddress((void**)&p_w2l, g_w2l);

    cudaFuncSetAttribute(mm_tc_kernel, cudaFuncAttributeMaxDynamicSharedMemorySize,
                         MM_DSMEM);

    // 0) operand conversions
    split_kernel<<<(M_ROWS * DMODEL / 4 + 255) / 256, 256>>>(x, p_a1h, p_a1l,
                                                             M_ROWS * DMODEL / 4);
    transpose_split_kernel<<<dim3(NXZ / 32, DMODEL / 32), 256>>>(W_in, p_w1h, p_w1l,
                                                                 DMODEL, NXZ);
    transpose_split_kernel<<<dim3(DMODEL / 32, DINNER / 32), 256>>>(W_out, p_w2h, p_w2l,
                                                                    DINNER, DMODEL);
    // 1) xz = x @ W_in + b_in  (HMMA split-bf16, cp.async pipelined)
    mm_tc_kernel<<<dim3(NXZ / 128, M_ROWS / 128), 256, MM_DSMEM>>>(
        p_a1h, p_a1l, p_w1h, p_w1l, b_in, p_xz, M_ROWS, NXZ, DMODEL);
    // 2) conv + silu -> g_xc
    conv_silu_kernel<<<dim3(DINNER / 256, M_ROWS), 256>>>(conv_w, conv_b);
    // 3) uniformity check
    cudaMemsetAsync(p_flag, 0, sizeof(int));
    check_kernel<<<(DINNER * DSTATE + 255) / 256, 256>>>(A_log);
    // 4) projection (split-K x8) + coefficients
    proj_gemm_kernel<<<dim3(M_ROWS / 32, KSPLIT), 256>>>(W_xproj);
    coef_kernel<<<(M_ROWS * DSTATE) / 256, 256>>>(A_log);
    // 5) local scans (+ fused chunk prefix products)
    scan_local_kernel<<<NCHUNK * 16, 128>>>();
    // 6) carry scan
    carry_kernel<<<(BATCH * DINNER * DSTATE) / 256, 256>>>();
    // 7) combine + gated epilogue + fused y split -> yh/yl
    finish_kernel<<<NCHUNK * 16, 128>>>(D_param);
    // 8) fallback (early-exits when A uniform)
    scan_fallback_kernel<<<128, 32>>>(D_param, A_log);
    // 9) out = y @ W_out + b_out (HMMA pipelined)
    mm_tc_kernel<<<dim3(DMODEL / 128, M_ROWS / 128), 256, MM_DSMEM>>>(
        p_yh, p_yl, p_w2h, p_w2l, b_out, out, M_ROWS, DMODEL, DINNER);
}

// round 16
// speedup vs baseline: 1.2664x; 1.0350x over previous
#include <cuda_runtime.h>
#include <cuda_bf16.h>
#include <math.h>
#include <stdint.h>

#define BATCH   2
#define SEQLEN  2048
#define DMODEL  1024
#define DINNER  2048
#define DSTATE  16
#define DCONV   4
#define M_ROWS  (BATCH * SEQLEN)   // 4096
#define NXZ     (2 * DINNER)       // 4096
#define CHUNK   32
#define NCHUNK  (M_ROWS / CHUNK)   // 128
#define NCH_B   (SEQLEN / CHUNK)   // 64
#define NPROJ   33
#define KSPLIT  8

// ---------------- scratch (static device arrays) ----------------
__device__ float g_xz[M_ROWS * NXZ];           // 64 MB
__device__ float g_xc[M_ROWS * DINNER];        // 32 MB
__device__ float g_y [M_ROWS * DINNER];        // y_local (scan) 32 MB
__device__ float g_projp[KSPLIT * M_ROWS * NPROJ];
__device__ float g_coef[M_ROWS * 48];
__device__ float g_delta[M_ROWS];
__device__ float g_wpre[M_ROWS * DSTATE];
__device__ float g_Ac[NCHUNK * DSTATE];
__device__ float g_hloc [NCHUNK * DINNER * DSTATE];
__device__ float g_hstart[NCHUNK * DINNER * DSTATE];
__device__ int   g_nonuni;

// split-bf16 operands
__device__ __nv_bfloat16 g_a1h[M_ROWS * DMODEL], g_a1l[M_ROWS * DMODEL];   // x hi/lo
__device__ __nv_bfloat16 g_w1h[NXZ * DMODEL],    g_w1l[NXZ * DMODEL];      // W_in^T [N][K]
__device__ __nv_bfloat16 g_yh [M_ROWS * DINNER], g_yl [M_ROWS * DINNER];   // y hi/lo
__device__ __nv_bfloat16 g_w2h[DMODEL * DINNER], g_w2l[DMODEL * DINNER];   // W_out^T [N][K]

// ---------------- helpers ----------------
__device__ __forceinline__ uint32_t smem_to_u32(const void* p) {
    uint32_t a;
    asm("{ .reg .u64 t; cvta.to.shared.u64 t, %1; cvt.u32.u64 %0, t; }" : "=r"(a) : "l"(p));
    return a;
}

__device__ __forceinline__ void ldsm_x4(uint32_t& r0, uint32_t& r1, uint32_t& r2, uint32_t& r3,
                                        uint32_t addr) {
    asm volatile("ldmatrix.sync.aligned.m8n8.x4.shared.b16 {%0,%1,%2,%3}, [%4];"
                 : "=r"(r0), "=r"(r1), "=r"(r2), "=r"(r3) : "r"(addr));
}

__device__ __forceinline__ void mma_bf16(float& d0, float& d1, float& d2, float& d3,
                                         uint32_t a0, uint32_t a1, uint32_t a2, uint32_t a3,
                                         uint32_t b0, uint32_t b1) {
    asm volatile("mma.sync.aligned.m16n8k16.row.col.f32.bf16.bf16.f32 "
                 "{%0,%1,%2,%3}, {%4,%5,%6,%7}, {%8,%9}, {%0,%1,%2,%3};"
                 : "+f"(d0), "+f"(d1), "+f"(d2), "+f"(d3)
                 : "r"(a0), "r"(a1), "r"(a2), "r"(a3), "r"(b0), "r"(b1));
}

__device__ __forceinline__ void cp_async16(uint32_t dst, const void* src) {
    asm volatile("cp.async.cg.shared.global [%0], [%1], 16;" :: "r"(dst), "l"(src));
}
#define CP_COMMIT() asm volatile("cp.async.commit_group;" ::: "memory")
#define CP_WAIT1()  asm volatile("cp.async.wait_group 1;" ::: "memory")

// ---------------------------------------------------------------------------
// Split-bf16 tensor-core GEMM via mma.sync (HMMA), cp.async double-buffered.
// PROVEN SHAPE: 128x128 CTA tile, 256 threads, 8 warps (4m x 2n),
// warp tile 32x64 (2 m16 x 8 n8), KTILE=32, two 40KB stages -> 2 CTAs/SM.
// 3 passes: Ah*Bh + Ah*Bl + Al*Bh (fp32 accum). Rows padded to 40 bf16 (80B).
// ldc lets a launch write a column block of a wider C matrix.
// ---------------------------------------------------------------------------
#define KTILE 32
#define ROWP  40                      // padded row length in bf16 (80 bytes)
#define MATB  (128 * ROWP * 2)        // 10240 bytes per matrix
#define STAGEB (4 * MATB)             // 40960 bytes per stage
#define MM_DSMEM (2 * STAGEB)         // 81920

__global__ __launch_bounds__(256)
void mm_tc_kernel(const __nv_bfloat16* __restrict__ Ah, const __nv_bfloat16* __restrict__ Al,
                  const __nv_bfloat16* __restrict__ Bh, const __nv_bfloat16* __restrict__ Bl,
                  const float* __restrict__ bias, float* __restrict__ C,
                  int M, int K, int ldc)
{
    extern __shared__ __align__(16) char dynsm[];
    const uint32_t sbase = smem_to_u32(dynsm);

    const int tid  = threadIdx.x;
    const int wid  = tid >> 5;
    const int lane = tid & 31;
    const int n0 = blockIdx.x * 128;
    const int m0 = blockIdx.y * 128;

    const int wm = wid >> 1;        // 0..3 -> m offset wm*32
    const int wn = wid & 1;         // 0..1 -> n offset wn*64

    float acc[2][8][4];             // [mt][nt][frag]
#pragma unroll
    for (int i = 0; i < 2; i++)
#pragma unroll
        for (int j = 0; j < 8; j++)
#pragma unroll
            for (int q = 0; q < 4; q++) acc[i][j][q] = 0.f;

    const uint32_t a_row  = (uint32_t)(wm * 32 + (lane & 15));
    const uint32_t a_coff = (uint32_t)((lane >> 4) * 16);
    const uint32_t b_row  = (uint32_t)(wn * 64 + (lane & 7) + ((lane >> 4) << 3));
    const uint32_t b_koff = (uint32_t)(((lane >> 3) & 1) * 16);

    const int nk = K / KTILE;

    // ---- prologue: async-load k-tile 0 into stage 0 ----
#pragma unroll
    for (int j = 0; j < 8; j++) {
        int i    = tid + j * 256;
        int mId  = i >> 9;
        int w    = i & 511;
        int row  = w >> 2;
        int c4   = w & 3;
        const __nv_bfloat16* src =
            (mId == 0) ? Ah : (mId == 1) ? Al : (mId == 2) ? Bh : Bl;
        const int r0 = (mId < 2) ? m0 : n0;
        cp_async16(sbase + mId * MATB + (uint32_t)(row * 80 + c4 * 16),
                   src + (size_t)(r0 + row) * K + c4 * 8);
    }
    CP_COMMIT();

    for (int kt = 0; kt < nk; kt++) {
        const int cur = kt & 1;
        if (kt + 1 < nk) {
            const int k1 = (kt + 1) * KTILE;
            const uint32_t stoff = (uint32_t)((cur ^ 1) * STAGEB);
#pragma unroll
            for (int j = 0; j < 8; j++) {
                int i    = tid + j * 256;
                int mId  = i >> 9;
                int w    = i & 511;
                int row  = w >> 2;
                int c4   = w & 3;
                const __nv_bfloat16* src =
                    (mId == 0) ? Ah : (mId == 1) ? Al : (mId == 2) ? Bh : Bl;
                const int r0 = (mId < 2) ? m0 : n0;
                cp_async16(sbase + stoff + mId * MATB + (uint32_t)(row * 80 + c4 * 16),
                           src + (size_t)(r0 + row) * K + k1 + c4 * 8);
            }
        }
        CP_COMMIT();
        CP_WAIT1();
        __syncthreads();

        const uint32_t sb = sbase + (uint32_t)(cur * STAGEB);
#pragma unroll
        for (int kk = 0; kk < 2; kk++) {
            uint32_t ah[2][4], al[2][4];
#pragma unroll
            for (int mt = 0; mt < 2; mt++) {
                uint32_t off = (a_row + mt * 16) * 80 + kk * 32 + a_coff;
                ldsm_x4(ah[mt][0], ah[mt][1], ah[mt][2], ah[mt][3], sb + off);
                ldsm_x4(al[mt][0], al[mt][1], al[mt][2], al[mt][3], sb + MATB + off);
            }
            uint32_t bh[8][2], bl[8][2];
#pragma unroll
            for (int np = 0; np < 4; np++) {
                uint32_t off = (b_row + np * 16) * 80 + kk * 32 + b_koff;
                uint32_t r0, r1, r2, r3;
                ldsm_x4(r0, r1, r2, r3, sb + 2 * MATB + off);
                bh[np*2][0] = r0; bh[np*2][1] = r1; bh[np*2+1][0] = r2; bh[np*2+1][1] = r3;
                ldsm_x4(r0, r1, r2, r3, sb + 3 * MATB + off);
                bl[np*2][0] = r0; bl[np*2][1] = r1; bl[np*2+1][0] = r2; bl[np*2+1][1] = r3;
            }
#pragma unroll
            for (int mt = 0; mt < 2; mt++)
#pragma unroll
                for (int nt = 0; nt < 8; nt++) {
                    float* d = acc[mt][nt];
                    mma_bf16(d[0], d[1], d[2], d[3],
                             ah[mt][0], ah[mt][1], ah[mt][2], ah[mt][3],
                             bh[nt][0], bh[nt][1]);
                    mma_bf16(d[0], d[1], d[2], d[3],
                             ah[mt][0], ah[mt][1], ah[mt][2], ah[mt][3],
                             bl[nt][0], bl[nt][1]);
                    mma_bf16(d[0], d[1], d[2], d[3],
                             al[mt][0], al[mt][1], al[mt][2], al[mt][3],
                             bh[nt][0], bh[nt][1]);
                }
        }
        __syncthreads();
    }

    // ---- epilogue
    const int rbase = m0 + wm * 32 + (lane >> 2);
    const int cbase = n0 + wn * 64 + (lane & 3) * 2;
#pragma unroll
    for (int mt = 0; mt < 2; mt++) {
#pragma unroll
        for (int nt = 0; nt < 8; nt++) {
            int r = rbase + mt * 16;
            int c = cbase + nt * 8;
            float b0 = bias[c], b1 = bias[c + 1];
            float2 o0 = { acc[mt][nt][0] + b0, acc[mt][nt][1] + b1 };
            float2 o1 = { acc[mt][nt][2] + b0, acc[mt][nt][3] + b1 };
            *(float2*)(C + (size_t)r * ldc + c)       = o0;
            *(float2*)(C + (size_t)(r + 8) * ldc + c) = o1;
        }
    }
}

// ---------------------------------------------------------------------------
// fp32 -> (hi, lo) bf16 split, elementwise, vectorized.
// ---------------------------------------------------------------------------
__global__ __launch_bounds__(256)
void split_kernel(const float* __restrict__ src, __nv_bfloat16* __restrict__ h,
                  __nv_bfloat16* __restrict__ l, int n4)
{
    int i = blockIdx.x * 256 + threadIdx.x;
    if (i >= n4) return;
    float4 v = ((const float4*)src)[i];
    float f[4] = { v.x, v.y, v.z, v.w };
    __nv_bfloat16 hh[4], ll[4];
#pragma unroll
    for (int j = 0; j < 4; j++) {
        hh[j] = __float2bfloat16(f[j]);
        ll[j] = __float2bfloat16(f[j] - __bfloat162float(hh[j]));
    }
    ((ushort4*)h)[i] = *(ushort4*)hh;
    ((ushort4*)l)[i] = *(ushort4*)ll;
}

// ---------------------------------------------------------------------------
// W[K][N] -> T[N][K] transpose with hi/lo bf16 split. 32x32 tiles.
// ---------------------------------------------------------------------------
__global__ __launch_bounds__(256)
void transpose_split_kernel(const float* __restrict__ W, __nv_bfloat16* __restrict__ Th,
                            __nv_bfloat16* __restrict__ Tl, int K, int N)
{
    __shared__ float tile[32][33];
    const int nb = blockIdx.x * 32;
    const int kb = blockIdx.y * 32;
    const int tx = threadIdx.x & 31;
    const int ty = threadIdx.x >> 5;
#pragma unroll
    for (int i = 0; i < 32; i += 8)
        tile[ty + i][tx] = W[(size_t)(kb + ty + i) * N + nb + tx];
    __syncthreads();
#pragma unroll
    for (int i = 0; i < 32; i += 8) {
        float v = tile[tx][ty + i];
        __nv_bfloat16 h = __float2bfloat16(v);
        __nv_bfloat16 l = __float2bfloat16(v - __bfloat162float(h));
        Th[(size_t)(nb + ty + i) * K + kb + tx] = h;
        Tl[(size_t)(nb + ty + i) * K + kb + tx] = l;
    }
}

// ---------------------------------------------------------------------------
// Causal depthwise conv (width 4) + SiLU. Reads x_ssm half of g_xz only.
// ---------------------------------------------------------------------------
__global__ __launch_bounds__(256)
void conv_silu_kernel(const float* __restrict__ conv_w, const float* __restrict__ conv_b)
{
    const int m = blockIdx.y;
    const int d = blockIdx.x * 256 + threadIdx.x;
    const int t = m & (SEQLEN - 1);

    float4 w = *(const float4*)(conv_w + d * 4);
    float acc = conv_b[d];
    const float* base = g_xz + (size_t)m * NXZ + d;

    if (t >= 3) {
        acc = fmaf(base[-3 * NXZ], w.x, acc);
        acc = fmaf(base[-2 * NXZ], w.y, acc);
        acc = fmaf(base[-1 * NXZ], w.z, acc);
        acc = fmaf(base[0],        w.w, acc);
    } else {
        const float wk[4] = { w.x, w.y, w.z, w.w };
#pragma unroll
        for (int k = 0; k < 4; k++) {
            int ts = t - 3 + k;
            if (ts >= 0) acc = fmaf(base[(k - 3) * NXZ], wk[k], acc);
        }
    }
    float s = acc / (1.f + expf(-acc));
    g_xc[(size_t)m * DINNER + d] = s;
}

// ---------------------------------------------------------------------------
__global__ void check_kernel(const float* __restrict__ A_log)
{
    int idx = blockIdx.x * blockDim.x + threadIdx.x;
    if (idx < DINNER * DSTATE) {
        if (A_log[idx] != A_log[idx & 15]) atomicOr(&g_nonuni, 1);
    }
}

// ---------------------------------------------------------------------------
// proj partials: slice ks covers K range [ks*256, ks*256+256).
// ---------------------------------------------------------------------------
#define PBK 64
__global__ __launch_bounds__(256)
void proj_gemm_kernel(const float* __restrict__ W_xproj)
{
    __shared__ float As[PBK][33];
    __shared__ float Ws[PBK][36];

    const int tid = threadIdx.x;
    const int m0  = blockIdx.x * 32;
    const int ks  = blockIdx.y;
    const int kb  = ks * (DINNER / KSPLIT);

    const int r  = tid & 31;
    const int tc = tid >> 5;

    float acc[4] = {0.f, 0.f, 0.f, 0.f};
    float acc32  = 0.f;

    for (int k0 = kb; k0 < kb + DINNER / KSPLIT; k0 += PBK) {
#pragma unroll
        for (int i = 0; i < 2; i++) {
            int f    = tid + i * 256;
            int row  = f >> 4;
            int col4 = f & 15;
            float4 v = *(const float4*)(g_xc + (size_t)(m0 + row) * DINNER + k0 + col4 * 4);
            As[col4 * 4 + 0][row] = v.x;
            As[col4 * 4 + 1][row] = v.y;
            As[col4 * 4 + 2][row] = v.z;
            As[col4 * 4 + 3][row] = v.w;
        }
        for (int idx = tid; idx < PBK * NPROJ; idx += 256) {
            int k = idx / NPROJ;
            int j = idx - k * NPROJ;
            Ws[k][j] = W_xproj[(size_t)(k0 + k) * NPROJ + j];
        }
        __syncthreads();

#pragma unroll 8
        for (int k = 0; k < PBK; k++) {
            float a  = As[k][r];
            float4 w = *(const float4*)(&Ws[k][tc * 4]);
            acc[0] = fmaf(a, w.x, acc[0]);
            acc[1] = fmaf(a, w.y, acc[1]);
            acc[2] = fmaf(a, w.z, acc[2]);
            acc[3] = fmaf(a, w.w, acc[3]);
            if (tc == 0) acc32 = fmaf(a, Ws[k][32], acc32);
        }
        __syncthreads();
    }

    float* prow = g_projp + ((size_t)ks * M_ROWS + m0 + r) * NPROJ;
#pragma unroll
    for (int jj = 0; jj < 4; jj++)
        prow[tc * 4 + jj] = acc[jj];
    if (tc == 0) prow[32] = acc32;
}

// ---------------------------------------------------------------------------
// Coefficients (sums the KSPLIT partials). One thread per (m, n).
// ---------------------------------------------------------------------------
__global__ __launch_bounds__(256)
void coef_kernel(const float* __restrict__ A_log)
{
    const int idx = blockIdx.x * 256 + threadIdx.x;
    const int m = idx >> 4;
    const int n = idx & 15;

    float pn = 0.f, pc = 0.f, pd = 0.f;
#pragma unroll
    for (int s = 0; s < KSPLIT; s++) {
        const float* p = g_projp + ((size_t)s * M_ROWS + m) * NPROJ;
        pn += p[n];
        pc += p[16 + n];
        pd += p[32];
    }
    float delta = (pd > 20.f) ? pd : log1pf(expf(pd));

    float An = -expf(A_log[n]);
    g_coef[(size_t)m * 48 + n]      = expf(delta * An);
    g_coef[(size_t)m * 48 + 16 + n] = delta * pn;
    g_coef[(size_t)m * 48 + 32 + n] = pc;
    if (n == 0) g_delta[m] = delta;
}

// ---------------------------------------------------------------------------
// Phase 1: local scans. 128 threads = 4 warps share one coef-tile load.
// dg==0 blocks also compute the chunk prefix products. grid = NCHUNK*16.
// ---------------------------------------------------------------------------
__global__ __launch_bounds__(128)
void scan_local_kernel()
{
    const int tid  = threadIdx.x;
    const int lane = tid & 31;
    const int wd   = tid >> 5;
    const int c    = blockIdx.x >> 4;
    const int dg   = blockIdx.x & 15;
    const int d    = dg * 128 + wd * 32 + lane;
    const int mbase = c * CHUNK;

    __shared__ float4 sc[CHUNK][12];
    __shared__ float  sx[CHUNK][128];

    {
        const float4* src = (const float4*)(g_coef + (size_t)mbase * 48);
        float4* dst = (float4*)sc;
#pragma unroll
        for (int i = 0; i < 3; i++)
            dst[tid + i * 128] = src[tid + i * 128];
#pragma unroll
        for (int i = 0; i < CHUNK; i++)
            sx[i][wd * 32 + lane] = g_xc[(size_t)(mbase + i) * DINNER + d];
    }
    __syncthreads();

    float h[16];
#pragma unroll
    for (int n = 0; n < 16; n++) h[n] = 0.f;

#pragma unroll 8
    for (int tt = 0; tt < CHUNK; tt++) {
        const float x = sx[tt][wd * 32 + lane];
        float y = 0.f;
#pragma unroll
        for (int q = 0; q < 4; q++) {
            float4 a4 = sc[tt][q];
            float4 b4 = sc[tt][4 + q];
            float4 c4 = sc[tt][8 + q];
            h[4*q+0] = fmaf(a4.x, h[4*q+0], b4.x * x); y = fmaf(h[4*q+0], c4.x, y);
            h[4*q+1] = fmaf(a4.y, h[4*q+1], b4.y * x); y = fmaf(h[4*q+1], c4.y, y);
            h[4*q+2] = fmaf(a4.z, h[4*q+2], b4.z * x); y = fmaf(h[4*q+2], c4.z, y);
            h[4*q+3] = fmaf(a4.w, h[4*q+3], b4.w * x); y = fmaf(h[4*q+3], c4.w, y);
        }
        g_y[(size_t)(mbase + tt) * DINNER + d] = y;
    }

    float* hl = g_hloc + ((size_t)c * DINNER + d) * DSTATE;
#pragma unroll
    for (int q = 0; q < 4; q++)
        *(float4*)(hl + 4 * q) = make_float4(h[4*q], h[4*q+1], h[4*q+2], h[4*q+3]);

    if (dg == 0 && tid < 16) {
        const float* scf = (const float*)sc;
        float P = 1.f;
#pragma unroll
        for (int tt = 0; tt < CHUNK; tt++) {
            P *= scf[tt * 48 + tid];
            g_wpre[(size_t)(mbase + tt) * DSTATE + tid] = scf[tt * 48 + 32 + tid] * P;
        }
        g_Ac[c * DSTATE + tid] = P;
    }
}

// ---------------------------------------------------------------------------
__global__ __launch_bounds__(256)
void carry_kernel()
{
    const int idx = blockIdx.x * 256 + threadIdx.x;
    const int b = idx >> 15;
    const int d = (idx >> 4) & (DINNER - 1);
    const int n = idx & 15;

    float h = 0.f;
    for (int cl = 0; cl < NCH_B; cl++) {
        const int c = b * NCH_B + cl;
        const size_t off = ((size_t)c * DINNER + d) * DSTATE + n;
        g_hstart[off] = h;
        h = fmaf(g_Ac[c * DSTATE + n], h, g_hloc[off]);
    }
}

// ---------------------------------------------------------------------------
// Phase 3: combine + gated epilogue + fused y hi/lo split. grid = NCHUNK*16.
// ---------------------------------------------------------------------------
__global__ __launch_bounds__(128)
void finish_kernel(const float* __restrict__ D_param)
{
    const int tid  = threadIdx.x;
    const int lane = tid & 31;
    const int wd   = tid >> 5;
    const int c    = blockIdx.x >> 4;
    const int dg   = blockIdx.x & 15;
    const int d    = dg * 128 + wd * 32 + lane;
    const int mbase = c * CHUNK;

    __shared__ float4 sw[CHUNK * 4];
    {
        const float4* src = (const float4*)(g_wpre + (size_t)mbase * DSTATE);
        sw[tid] = src[tid];
    }

    float hs[16];
    {
        const float* hp = g_hstart + ((size_t)c * DINNER + d) * DSTATE;
#pragma unroll
        for (int q = 0; q < 4; q++) {
            float4 v = *(const float4*)(hp + 4 * q);
            hs[4*q] = v.x; hs[4*q+1] = v.y; hs[4*q+2] = v.z; hs[4*q+3] = v.w;
        }
    }
    const float Dp = D_param[d];
    __syncthreads();

#pragma unroll 8
    for (int tt = 0; tt < CHUNK; tt++) {
        const int m = mbase + tt;
        float y = g_y[(size_t)m * DINNER + d];
#pragma unroll
        for (int q = 0; q < 4; q++) {
            float4 w4 = sw[tt * 4 + q];
            y = fmaf(w4.x, hs[4*q+0], y);
            y = fmaf(w4.y, hs[4*q+1], y);
            y = fmaf(w4.z, hs[4*q+2], y);
            y = fmaf(w4.w, hs[4*q+3], y);
        }
        const float x = g_xc[(size_t)m * DINNER + d];
        const float z = g_xz[(size_t)m * NXZ + DINNER + d];
        const float sz = z / (1.f + expf(-z));
        const float yv = (y + x * Dp) * sz;
        __nv_bfloat16 hh = __float2bfloat16(yv);
        __nv_bfloat16 ll = __float2bfloat16(yv - __bfloat162float(hh));
        g_yh[(size_t)m * DINNER + d] = hh;
        g_yl[(size_t)m * DINNER + d] = ll;
    }
}

// ---------------------------------------------------------------------------
// Fallback: full sequential scan (only if A non-uniform). Writes yh/yl.
// ---------------------------------------------------------------------------
__global__ __launch_bounds__(32)
void scan_fallback_kernel(const float* __restrict__ D_param, const float* __restrict__ A_log)
{
    if (*((volatile int*)&g_nonuni) == 0) return;

    const int lane  = threadIdx.x;
    const int b     = blockIdx.x >> 6;
    const int d     = (blockIdx.x & 63) * 32 + lane;
    const int mbase = b * SEQLEN;

    const float Dp = D_param[d];
    float Aloc[16];
#pragma unroll
    for (int n = 0; n < 16; n++) Aloc[n] = -expf(A_log[d * 16 + n]);

    float h[16];
#pragma unroll
    for (int n = 0; n < 16; n++) h[n] = 0.f;

    __shared__ float4 sc[32][12];

    for (int t0 = 0; t0 < SEQLEN; t0 += 32) {
        __syncthreads();
        const float4* src = (const float4*)(g_coef + (size_t)(mbase + t0) * 48);
        float4* dst = (float4*)sc;
#pragma unroll
        for (int i = 0; i < 12; i++)
            dst[lane + i * 32] = src[lane + i * 32];
        __syncthreads();

        for (int tt = 0; tt < 32; tt++) {
            const int m = mbase + t0 + tt;
            const float x = g_xc[(size_t)m * DINNER + d];
            const float dlt = g_delta[m];
            float y = 0.f;
#pragma unroll
            for (int q = 0; q < 4; q++) {
                float4 b4 = sc[tt][4 + q];
                float4 c4 = sc[tt][8 + q];
                float a0 = expf(dlt * Aloc[4*q+0]);
                float a1 = expf(dlt * Aloc[4*q+1]);
                float a2 = expf(dlt * Aloc[4*q+2]);
                float a3 = expf(dlt * Aloc[4*q+3]);
                h[4*q+0] = fmaf(a0, h[4*q+0], b4.x * x); y = fmaf(h[4*q+0], c4.x, y);
                h[4*q+1] = fmaf(a1, h[4*q+1], b4.y * x); y = fmaf(h[4*q+1], c4.y, y);
                h[4*q+2] = fmaf(a2, h[4*q+2], b4.z * x); y = fmaf(h[4*q+2], c4.z, y);
                h[4*q+3] = fmaf(a3, h[4*q+3], b4.w * x); y = fmaf(h[4*q+3], c4.w, y);
            }
            float z  = g_xz[(size_t)m * NXZ + DINNER + d];
            float sz = z / (1.f + expf(-z));
            const float yv = (y + x * Dp) * sz;
            __nv_bfloat16 hh = __float2bfloat16(yv);
            __nv_bfloat16 ll = __float2bfloat16(yv - __bfloat162float(hh));
            g_yh[(size_t)m * DINNER + d] = hh;
            g_yl[(size_t)m * DINNER + d] = ll;
        }
    }
}

// ---------------------------------------------------------------------------
extern "C" void kernel_launch(void* const* d_in, const int* in_sizes, int n_in,
                              void* d_out, int out_size)
{
    const float* x       = (const float*)d_in[0];
    const float* W_in    = (const float*)d_in[1];
    const float* b_in    = (const float*)d_in[2];
    const float* conv_w  = (const float*)d_in[3];
    const float* conv_b  = (const float*)d_in[4];
    const float* W_xproj = (const float*)d_in[5];
    const float* A_log   = (const float*)d_in[6];
    const float* D_param = (const float*)d_in[7];
    const float* W_out   = (const float*)d_in[8];
    const float* b_out   = (const float*)d_in[9];
    float* out = (float*)d_out;

    float *p_xz;
    void  *p_flag;
    __nv_bfloat16 *p_a1h, *p_a1l, *p_w1h, *p_w1l, *p_yh, *p_yl, *p_w2h, *p_w2l;
    cudaGetSymbolAddress((void**)&p_xz,  g_xz);
    cudaGetSymbolAddress(&p_flag, g_nonuni);
    cudaGetSymbolAddress((void**)&p_a1h, g_a1h);
    cudaGetSymbolAddress((void**)&p_a1l, g_a1l);
    cudaGetSymbolAddress((void**)&p_w1h, g_w1h);
    cudaGetSymbolAddress((void**)&p_w1l, g_w1l);
    cudaGetSymbolAddress((void**)&p_yh,  g_yh);
    cudaGetSymbolAddress((void**)&p_yl,  g_yl);
    cudaGetSymbolAddress((void**)&p_w2h, g_w2h);
    cudaGetSymbolAddress((void**)&p_w2l, g_w2l);

    cudaFuncSetAttribute(mm_tc_kernel, cudaFuncAttributeMaxDynamicSharedMemorySize,
                         MM_DSMEM);

    // one-time side stream + fork/join events (host resources, not device mem)
    static cudaStream_t s2 = nullptr;
    static cudaEvent_t  evFork = nullptr, evJoin = nullptr;
    if (s2 == nullptr) {
        cudaStreamCreateWithFlags(&s2, cudaStreamNonBlocking);
        cudaEventCreateWithFlags(&evFork, cudaEventDisableTiming);
        cudaEventCreateWithFlags(&evJoin, cudaEventDisableTiming);
    }

    // 0) operand conversions (main stream)
    split_kernel<<<(M_ROWS * DMODEL / 4 + 255) / 256, 256>>>(x, p_a1h, p_a1l,
                                                             M_ROWS * DMODEL / 4);
    transpose_split_kernel<<<dim3(NXZ / 32, DMODEL / 32), 256>>>(W_in, p_w1h, p_w1l,
                                                                 DMODEL, NXZ);

    // ---- fork: side stream handles W_out transpose + GEMM1-z half ----
    cudaEventRecord(evFork, 0);
    cudaStreamWaitEvent(s2, evFork, 0);

    //   side stream: W_out conversion, then z-half of xz (cols 2048..4095)
    transpose_split_kernel<<<dim3(DMODEL / 32, DINNER / 32), 256, 0, s2>>>(
        W_out, p_w2h, p_w2l, DINNER, DMODEL);
    mm_tc_kernel<<<dim3(DINNER / 128, M_ROWS / 128), 256, MM_DSMEM, s2>>>(
        p_a1h, p_a1l,
        p_w1h + (size_t)DINNER * DMODEL, p_w1l + (size_t)DINNER * DMODEL,
        b_in + DINNER, p_xz + DINNER, M_ROWS, DMODEL, NXZ);
    cudaEventRecord(evJoin, s2);

    //   main stream: x-half of xz (cols 0..2047), then the scan chain
    mm_tc_kernel<<<dim3(DINNER / 128, M_ROWS / 128), 256, MM_DSMEM>>>(
        p_a1h, p_a1l, p_w1h, p_w1l, b_in, p_xz, M_ROWS, DMODEL, NXZ);
    conv_silu_kernel<<<dim3(DINNER / 256, M_ROWS), 256>>>(conv_w, conv_b);
    cudaMemsetAsync(p_flag, 0, sizeof(int));
    check_kernel<<<(DINNER * DSTATE + 255) / 256, 256>>>(A_log);
    proj_gemm_kernel<<<dim3(M_ROWS / 32, KSPLIT), 256>>>(W_xproj);
    coef_kernel<<<(M_ROWS * DSTATE) / 256, 256>>>(A_log);
    scan_local_kernel<<<NCHUNK * 16, 128>>>();
    carry_kernel<<<(BATCH * DINNER * DSTATE) / 256, 256>>>();

    // ---- join: finish needs the z half ----
    cudaStreamWaitEvent(0, evJoin, 0);
    finish_kernel<<<NCHUNK * 16, 128>>>(D_param);
    scan_fallback_kernel<<<128, 32>>>(D_param, A_log);

    // out = y @ W_out + b_out
    mm_tc_kernel<<<dim3(DMODEL / 128, M_ROWS / 128), 256, MM_DSMEM>>>(
        p_yh, p_yl, p_w2h, p_w2l, b_out, out, M_ROWS, DINNER, DMODEL);
}